// round 1
// baseline (speedup 1.0000x reference)
#include <cuda_runtime.h>
#include <cuda_bf16.h>
#include <math.h>

// Problem constants: B=2, S=2048, D=2048, L=256, H=16, hd=128
#define BB   2
#define SS   2048
#define DD   2048
#define LL   256
#define HH   16
#define HD   128
#define MROWS (BB * SS)         // 4096

// ---------------------------------------------------------------------------
// Scratch (static device globals; no allocation allowed)
// ---------------------------------------------------------------------------
__device__ float g_q[(size_t)MROWS * DD];
__device__ float g_k[(size_t)MROWS * DD];
__device__ float g_v[(size_t)MROWS * DD];
__device__ float g_ctx[(size_t)MROWS * DD];
__device__ float g_latent[(size_t)MROWS * LL];

// ---------------------------------------------------------------------------
// SGEMM: C[M,N] = A[M,K] @ B[N,K]^T (+ bias[N])
// 128x128 tile, KT=8, 256 threads, 8x8 per-thread microtile.
// Requires M%128==0, N%128==0, K%8==0 (true for all shapes here).
// ---------------------------------------------------------------------------
__global__ __launch_bounds__(256) void sgemm_nt_kernel(
    const float* __restrict__ A, const float* __restrict__ B,
    const float* __restrict__ bias, float* __restrict__ C,
    int M, int N, int K)
{
    __shared__ float As[8][128];
    __shared__ float Bs[8][128];

    const int t    = threadIdx.x;
    const int row0 = blockIdx.y * 128;
    const int col0 = blockIdx.x * 128;
    const int tx   = t & 15;      // 0..15 -> C cols
    const int ty   = t >> 4;      // 0..15 -> C rows
    const int lr   = t >> 1;      // 0..127 load row within tile
    const int lc   = (t & 1) * 4; // 0 or 4 load col (k) offset

    const float* Aptr = A + (size_t)(row0 + lr) * K + lc;
    const float* Bptr = B + (size_t)(col0 + lr) * K + lc;

    float acc[8][8];
#pragma unroll
    for (int i = 0; i < 8; i++)
#pragma unroll
        for (int j = 0; j < 8; j++) acc[i][j] = 0.f;

    for (int k0 = 0; k0 < K; k0 += 8) {
        float4 av = *(const float4*)(Aptr + k0);
        float4 bv = *(const float4*)(Bptr + k0);
        __syncthreads();
        As[lc + 0][lr] = av.x; As[lc + 1][lr] = av.y;
        As[lc + 2][lr] = av.z; As[lc + 3][lr] = av.w;
        Bs[lc + 0][lr] = bv.x; Bs[lc + 1][lr] = bv.y;
        Bs[lc + 2][lr] = bv.z; Bs[lc + 3][lr] = bv.w;
        __syncthreads();
#pragma unroll
        for (int kk = 0; kk < 8; kk++) {
            float a[8], b[8];
            *(float4*)(a)     = *(const float4*)&As[kk][ty * 8];
            *(float4*)(a + 4) = *(const float4*)&As[kk][ty * 8 + 4];
            *(float4*)(b)     = *(const float4*)&Bs[kk][tx * 8];
            *(float4*)(b + 4) = *(const float4*)&Bs[kk][tx * 8 + 4];
#pragma unroll
            for (int i = 0; i < 8; i++)
#pragma unroll
                for (int j = 0; j < 8; j++)
                    acc[i][j] += a[i] * b[j];
        }
    }

#pragma unroll
    for (int i = 0; i < 8; i++) {
        size_t r = (size_t)(row0 + ty * 8 + i);
        float* crow = C + r * N + col0 + tx * 8;
#pragma unroll
        for (int j = 0; j < 8; j++) {
            float val = acc[i][j];
            if (bias) val += bias[col0 + tx * 8 + j];
            crow[j] = val;
        }
    }
}

// ---------------------------------------------------------------------------
// RoPE applied in-place to q and k.
// Layout: t[row = b*S+s][h*128 + j]; pairs (j, j+64), j in [0,64).
// ---------------------------------------------------------------------------
__global__ __launch_bounds__(256) void rope_kernel(float* __restrict__ q,
                                                   float* __restrict__ k)
{
    int idx = blockIdx.x * blockDim.x + threadIdx.x;
    const int total = MROWS * HH * 64;
    if (idx >= total) return;

    int j   = idx & 63;
    int h   = (idx >> 6) & (HH - 1);
    int row = idx >> 10;           // 64*16 = 1024 per row
    int s   = row & (SS - 1);

    // inv_freq = 10000^(-j/64) = 2^(-j/64 * log2(10000))
    const float LOG2_BASE = 13.287712379549449f; // log2(10000)
    float inv = exp2f(-(float)j * (LOG2_BASE / 64.0f));
    float ang = (float)s * inv;
    float c, sn;
    sincosf(ang, &sn, &c);

    size_t base = (size_t)row * DD + h * HD;

    float q1 = q[base + j], q2 = q[base + j + 64];
    q[base + j]      = q1 * c - q2 * sn;
    q[base + j + 64] = q2 * c + q1 * sn;

    float k1 = k[base + j], k2 = k[base + j + 64];
    k[base + j]      = k1 * c - k2 * sn;
    k[base + j + 64] = k2 * c + k1 * sn;
}

// ---------------------------------------------------------------------------
// Causal flash attention, fp32.
// grid = (S/64, H, B); 256 threads.
// Q/K/V tiles 64x128 in smem (pitch-padded), scores 64x64 in smem.
// Score phase: (ty,tx) 4x4 microtile. Softmax/PV phase: 4 threads per row,
// each owning 32 output columns.
// ---------------------------------------------------------------------------
#define FA_PITCH  132   // floats per 128-wide row (pad 4)
#define FA_SPITCH 65    // floats per 64-wide score row (pad 1)
#define FA_SMEM_FLOATS (3 * 64 * FA_PITCH + 64 * FA_SPITCH)
#define FA_SMEM_BYTES  (FA_SMEM_FLOATS * 4)

__global__ __launch_bounds__(256) void flash_kernel(
    const float* __restrict__ q, const float* __restrict__ k,
    const float* __restrict__ v, float* __restrict__ ctx)
{
    extern __shared__ float smem[];
    float* Qs = smem;                      // 64 x FA_PITCH
    float* Ks = Qs + 64 * FA_PITCH;        // 64 x FA_PITCH
    float* Vs = Ks + 64 * FA_PITCH;        // 64 x FA_PITCH
    float* Ss = Vs + 64 * FA_PITCH;        // 64 x FA_SPITCH

    const int qt = blockIdx.x;
    const int h  = blockIdx.y;
    const int b  = blockIdx.z;
    const int t  = threadIdx.x;

    const int q0 = qt * 64;
    const size_t base_bh = (size_t)b * SS * DD + (size_t)h * HD;

    // Load Q tile (64 rows x 128 cols) as float4s
    for (int e = t; e < 64 * 32; e += 256) {
        int row = e >> 5;
        int c4  = (e & 31) * 4;
        float4 val = *(const float4*)(q + base_bh + (size_t)(q0 + row) * DD + c4);
        *(float4*)&Qs[row * FA_PITCH + c4] = val;
    }

    const int r  = t >> 2;      // row 0..63 (softmax/PV mapping)
    const int g  = t & 3;       // sub-thread within row
    const int ty = t >> 4;      // score mapping
    const int tx = t & 15;
    const int i0 = ty * 4;
    const int j0 = tx * 4;
    const int c0 = g * 32;      // output column base for PV

    float m_run = -1e30f, l_run = 0.f;
    float oacc[32];
#pragma unroll
    for (int i = 0; i < 32; i++) oacc[i] = 0.f;

    const float scale = 0.088388347648318447f; // 1/sqrt(128)

    for (int kt = 0; kt <= qt; kt++) {
        __syncthreads();  // prev iter done with Ks/Vs/Ss
        // Load K and V tiles
        for (int e = t; e < 64 * 32; e += 256) {
            int row = e >> 5;
            int c4  = (e & 31) * 4;
            size_t gidx = base_bh + (size_t)(kt * 64 + row) * DD + c4;
            *(float4*)&Ks[row * FA_PITCH + c4] = *(const float4*)(k + gidx);
            *(float4*)&Vs[row * FA_PITCH + c4] = *(const float4*)(v + gidx);
        }
        __syncthreads();

        // ---- scores: 4x4 per thread over 128-dim dot products ----
        float sacc[4][4];
#pragma unroll
        for (int ii = 0; ii < 4; ii++)
#pragma unroll
            for (int jj = 0; jj < 4; jj++) sacc[ii][jj] = 0.f;

        for (int kk = 0; kk < HD; kk += 4) {
            float4 qv[4], kv[4];
#pragma unroll
            for (int ii = 0; ii < 4; ii++)
                qv[ii] = *(const float4*)&Qs[(i0 + ii) * FA_PITCH + kk];
#pragma unroll
            for (int jj = 0; jj < 4; jj++)
                kv[jj] = *(const float4*)&Ks[(j0 + jj) * FA_PITCH + kk];
#pragma unroll
            for (int ii = 0; ii < 4; ii++)
#pragma unroll
                for (int jj = 0; jj < 4; jj++)
                    sacc[ii][jj] += qv[ii].x * kv[jj].x + qv[ii].y * kv[jj].y +
                                    qv[ii].z * kv[jj].z + qv[ii].w * kv[jj].w;
        }
#pragma unroll
        for (int ii = 0; ii < 4; ii++)
#pragma unroll
            for (int jj = 0; jj < 4; jj++) {
                int gi = q0 + i0 + ii;
                int gj = kt * 64 + j0 + jj;
                Ss[(i0 + ii) * FA_SPITCH + (j0 + jj)] =
                    (gj <= gi) ? sacc[ii][jj] * scale : -1e30f;
            }
        __syncthreads();

        // ---- online softmax (4 threads per row) ----
        float mt = -1e30f;
        for (int j = g; j < 64; j += 4)
            mt = fmaxf(mt, Ss[r * FA_SPITCH + j]);
        mt = fmaxf(mt, __shfl_xor_sync(0xffffffffu, mt, 1));
        mt = fmaxf(mt, __shfl_xor_sync(0xffffffffu, mt, 2));

        float m_new  = fmaxf(m_run, mt);
        float factor = __expf(m_run - m_new);
        float lsum = 0.f;
        for (int j = g; j < 64; j += 4) {
            float p = __expf(Ss[r * FA_SPITCH + j] - m_new);
            Ss[r * FA_SPITCH + j] = p;
            lsum += p;
        }
        lsum += __shfl_xor_sync(0xffffffffu, lsum, 1);
        lsum += __shfl_xor_sync(0xffffffffu, lsum, 2);
        l_run = l_run * factor + lsum;
        m_run = m_new;
#pragma unroll
        for (int i = 0; i < 32; i++) oacc[i] *= factor;
        __syncthreads();

        // ---- PV accumulate: oacc[c0..c0+31] += P[r][:] @ V[:, c0..] ----
        for (int j = 0; j < 64; j++) {
            float p = Ss[r * FA_SPITCH + j];
            const float* vrow = &Vs[j * FA_PITCH + c0];
#pragma unroll
            for (int cc = 0; cc < 32; cc += 4) {
                float4 vv = *(const float4*)(vrow + cc);
                oacc[cc + 0] += p * vv.x;
                oacc[cc + 1] += p * vv.y;
                oacc[cc + 2] += p * vv.z;
                oacc[cc + 3] += p * vv.w;
            }
        }
    }

    float inv_l = 1.f / l_run;
    float* orow = ctx + base_bh + (size_t)(q0 + r) * DD + c0;
#pragma unroll
    for (int cc = 0; cc < 32; cc++) orow[cc] = oacc[cc] * inv_l;
}

// ---------------------------------------------------------------------------
// Launch
// ---------------------------------------------------------------------------
extern "C" void kernel_launch(void* const* d_in, const int* in_sizes, int n_in,
                              void* d_out, int out_size)
{
    const float* x    = (const float*)d_in[0];
    const float* wq   = (const float*)d_in[1];
    const float* wdkv = (const float*)d_in[2];
    const float* wuk  = (const float*)d_in[3];
    const float* wuv  = (const float*)d_in[4];
    const float* wo   = (const float*)d_in[5];
    const float* bo   = (const float*)d_in[6];
    float* out = (float*)d_out;

    float *qb, *kb, *vb, *ctxb, *latb;
    cudaGetSymbolAddress((void**)&qb,   g_q);
    cudaGetSymbolAddress((void**)&kb,   g_k);
    cudaGetSymbolAddress((void**)&vb,   g_v);
    cudaGetSymbolAddress((void**)&ctxb, g_ctx);
    cudaGetSymbolAddress((void**)&latb, g_latent);

    cudaFuncSetAttribute(flash_kernel,
                         cudaFuncAttributeMaxDynamicSharedMemorySize,
                         FA_SMEM_BYTES);

    // latent = x @ wdkv^T   [4096 x 256]
    sgemm_nt_kernel<<<dim3(LL / 128, MROWS / 128), 256>>>(
        x, wdkv, nullptr, latb, MROWS, LL, DD);
    // q = x @ wq^T          [4096 x 2048]
    sgemm_nt_kernel<<<dim3(DD / 128, MROWS / 128), 256>>>(
        x, wq, nullptr, qb, MROWS, DD, DD);
    // k = latent @ wuk^T
    sgemm_nt_kernel<<<dim3(DD / 128, MROWS / 128), 256>>>(
        latb, wuk, nullptr, kb, MROWS, DD, LL);
    // v = latent @ wuv^T
    sgemm_nt_kernel<<<dim3(DD / 128, MROWS / 128), 256>>>(
        latb, wuv, nullptr, vb, MROWS, DD, LL);

    // RoPE on q, k in place
    {
        int total = MROWS * HH * 64;
        rope_kernel<<<(total + 255) / 256, 256>>>(qb, kb);
    }

    // flash attention -> ctx
    flash_kernel<<<dim3(SS / 64, HH, BB), 256, FA_SMEM_BYTES>>>(qb, kb, vb, ctxb);

    // out = ctx @ wo^T + bo
    sgemm_nt_kernel<<<dim3(DD / 128, MROWS / 128), 256>>>(
        ctxb, wo, bo, out, MROWS, DD, DD);
}

// round 2
// speedup vs baseline: 2.1715x; 2.1715x over previous
#include <cuda_runtime.h>
#include <cuda_bf16.h>
#include <math.h>

// Problem constants: B=2, S=2048, D=2048, L=256, H=16, hd=128
#define BB   2
#define SS   2048
#define DD   2048
#define LL   256
#define HH   16
#define HD   128
#define MROWS (BB * SS)         // 4096

// ---------------------------------------------------------------------------
// Scratch (static device globals; no allocation allowed)
// ---------------------------------------------------------------------------
__device__ float g_q[(size_t)MROWS * DD];
__device__ float g_k[(size_t)MROWS * DD];
__device__ float g_v[(size_t)MROWS * DD];
__device__ float g_ctx[(size_t)MROWS * DD];
__device__ float g_latent[(size_t)MROWS * LL];

// ---------------------------------------------------------------------------
// SGEMM: C[M,N] = A[M,K] @ B[N,K]^T (+ bias[N])
// 128x128 tile, KT=8, 256 threads, 8x8 microtile, register prefetch.
// ---------------------------------------------------------------------------
__global__ __launch_bounds__(256) void sgemm_nt_kernel(
    const float* __restrict__ A, const float* __restrict__ B,
    const float* __restrict__ bias, float* __restrict__ C,
    int M, int N, int K)
{
    __shared__ float As[8][128];
    __shared__ float Bs[8][128];

    const int t    = threadIdx.x;
    const int row0 = blockIdx.y * 128;
    const int col0 = blockIdx.x * 128;
    const int tx   = t & 15;
    const int ty   = t >> 4;
    const int lr   = t >> 1;
    const int lc   = (t & 1) * 4;

    const float* Aptr = A + (size_t)(row0 + lr) * K + lc;
    const float* Bptr = B + (size_t)(col0 + lr) * K + lc;

    float acc[8][8];
#pragma unroll
    for (int i = 0; i < 8; i++)
#pragma unroll
        for (int j = 0; j < 8; j++) acc[i][j] = 0.f;

    float4 av = *(const float4*)(Aptr);
    float4 bv = *(const float4*)(Bptr);

    for (int k0 = 0; k0 < K; k0 += 8) {
        __syncthreads();
        As[lc + 0][lr] = av.x; As[lc + 1][lr] = av.y;
        As[lc + 2][lr] = av.z; As[lc + 3][lr] = av.w;
        Bs[lc + 0][lr] = bv.x; Bs[lc + 1][lr] = bv.y;
        Bs[lc + 2][lr] = bv.z; Bs[lc + 3][lr] = bv.w;
        __syncthreads();

        if (k0 + 8 < K) {           // prefetch next slab into registers
            av = *(const float4*)(Aptr + k0 + 8);
            bv = *(const float4*)(Bptr + k0 + 8);
        }

#pragma unroll
        for (int kk = 0; kk < 8; kk++) {
            float a[8], b[8];
            *(float4*)(a)     = *(const float4*)&As[kk][ty * 8];
            *(float4*)(a + 4) = *(const float4*)&As[kk][ty * 8 + 4];
            *(float4*)(b)     = *(const float4*)&Bs[kk][tx * 8];
            *(float4*)(b + 4) = *(const float4*)&Bs[kk][tx * 8 + 4];
#pragma unroll
            for (int i = 0; i < 8; i++)
#pragma unroll
                for (int j = 0; j < 8; j++)
                    acc[i][j] += a[i] * b[j];
        }
    }

#pragma unroll
    for (int i = 0; i < 8; i++) {
        size_t r = (size_t)(row0 + ty * 8 + i);
        float* crow = C + r * N + col0 + tx * 8;
#pragma unroll
        for (int j = 0; j < 8; j++) {
            float val = acc[i][j];
            if (bias) val += bias[col0 + tx * 8 + j];
            crow[j] = val;
        }
    }
}

// ---------------------------------------------------------------------------
// Small-N SGEMM: 64x64 tile, KT=16, 256 threads, 4x4 microtile, prefetch.
// Used for latent = x @ wdkv^T  (N=256 -> 256 blocks).
// ---------------------------------------------------------------------------
__global__ __launch_bounds__(256) void sgemm_nt64_kernel(
    const float* __restrict__ A, const float* __restrict__ B,
    float* __restrict__ C, int M, int N, int K)
{
    __shared__ float As[16][64];
    __shared__ float Bs[16][64];

    const int t    = threadIdx.x;
    const int row0 = blockIdx.y * 64;
    const int col0 = blockIdx.x * 64;
    const int tx   = t & 15;
    const int ty   = t >> 4;
    const int lr   = t & 63;          // conflict-free smem stores
    const int lc   = (t >> 6) * 4;

    const float* Aptr = A + (size_t)(row0 + lr) * K + lc;
    const float* Bptr = B + (size_t)(col0 + lr) * K + lc;

    float acc[4][4];
#pragma unroll
    for (int i = 0; i < 4; i++)
#pragma unroll
        for (int j = 0; j < 4; j++) acc[i][j] = 0.f;

    float4 av = *(const float4*)(Aptr);
    float4 bv = *(const float4*)(Bptr);

    for (int k0 = 0; k0 < K; k0 += 16) {
        __syncthreads();
        As[lc + 0][lr] = av.x; As[lc + 1][lr] = av.y;
        As[lc + 2][lr] = av.z; As[lc + 3][lr] = av.w;
        Bs[lc + 0][lr] = bv.x; Bs[lc + 1][lr] = bv.y;
        Bs[lc + 2][lr] = bv.z; Bs[lc + 3][lr] = bv.w;
        __syncthreads();

        if (k0 + 16 < K) {
            av = *(const float4*)(Aptr + k0 + 16);
            bv = *(const float4*)(Bptr + k0 + 16);
        }

#pragma unroll
        for (int kk = 0; kk < 16; kk++) {
            float a[4], b[4];
            *(float4*)(a) = *(const float4*)&As[kk][ty * 4];
            *(float4*)(b) = *(const float4*)&Bs[kk][tx * 4];
#pragma unroll
            for (int i = 0; i < 4; i++)
#pragma unroll
                for (int j = 0; j < 4; j++)
                    acc[i][j] += a[i] * b[j];
        }
    }

#pragma unroll
    for (int i = 0; i < 4; i++) {
        float* crow = C + (size_t)(row0 + ty * 4 + i) * N + col0 + tx * 4;
        float4 o;
        o.x = acc[i][0]; o.y = acc[i][1]; o.z = acc[i][2]; o.w = acc[i][3];
        *(float4*)crow = o;
    }
}

// ---------------------------------------------------------------------------
// RoPE applied in-place to q and k.
// ---------------------------------------------------------------------------
__global__ __launch_bounds__(256) void rope_kernel(float* __restrict__ q,
                                                   float* __restrict__ k)
{
    int idx = blockIdx.x * blockDim.x + threadIdx.x;
    const int total = MROWS * HH * 64;
    if (idx >= total) return;

    int j   = idx & 63;
    int h   = (idx >> 6) & (HH - 1);
    int row = idx >> 10;
    int s   = row & (SS - 1);

    const float LOG2_BASE = 13.287712379549449f; // log2(10000)
    float inv = exp2f(-(float)j * (LOG2_BASE / 64.0f));
    float ang = (float)s * inv;
    float c, sn;
    sincosf(ang, &sn, &c);

    size_t base = (size_t)row * DD + h * HD;

    float q1 = q[base + j], q2 = q[base + j + 64];
    q[base + j]      = q1 * c - q2 * sn;
    q[base + j + 64] = q2 * c + q1 * sn;

    float k1 = k[base + j], k2 = k[base + j + 64];
    k[base + j]      = k1 * c - k2 * sn;
    k[base + j + 64] = k2 * c + k1 * sn;
}

// ---------------------------------------------------------------------------
// Causal flash attention v2, fp32.
// grid = (S/64, H, B); 256 threads; Q/K transposed in smem (kk-major),
// V row-major; 4x4 score microtile, 4x8 PV microtile.
// ---------------------------------------------------------------------------
#define QK_P 68                 // pitch (floats) for transposed Q/K rows
#define V_P  132                // pitch for V rows (128 cols)
#define S_P  68                 // pitch for score rows (64 cols)
#define FA_SMEM_FLOATS (2 * 128 * QK_P + 64 * V_P + 64 * S_P + 128)
#define FA_SMEM_BYTES  (FA_SMEM_FLOATS * 4)

__global__ __launch_bounds__(256) void flash_kernel(
    const float* __restrict__ q, const float* __restrict__ k,
    const float* __restrict__ v, float* __restrict__ ctx)
{
    extern __shared__ float sm[];
    float* Qt = sm;                       // [128][QK_P] transposed
    float* Kt = Qt + 128 * QK_P;          // [128][QK_P] transposed
    float* Vs = Kt + 128 * QK_P;          // [64][V_P]
    float* Ss = Vs + 64 * V_P;            // [64][S_P]
    float* rowfac = Ss + 64 * S_P;        // [64]
    float* rowl   = rowfac + 64;          // [64]

    const int qt = blockIdx.x;
    const int h  = blockIdx.y;
    const int b  = blockIdx.z;
    const int t  = threadIdx.x;

    const int q0 = qt * 64;
    const size_t base_bh = (size_t)b * SS * DD + (size_t)h * HD;

    // Load Q tile transposed: Qt[kk][row]
    for (int e = t; e < 64 * 32; e += 256) {
        int row = e >> 5;
        int c4  = (e & 31) * 4;
        float4 val = *(const float4*)(q + base_bh + (size_t)(q0 + row) * DD + c4);
        Qt[(c4 + 0) * QK_P + row] = val.x;
        Qt[(c4 + 1) * QK_P + row] = val.y;
        Qt[(c4 + 2) * QK_P + row] = val.z;
        Qt[(c4 + 3) * QK_P + row] = val.w;
    }

    const int ty = t >> 4, tx = t & 15;
    const int i0 = ty * 4, j0 = tx * 4;
    const int r  = t >> 2, g = t & 3;     // softmax mapping

    float m_run = -1e30f, l_run = 0.f;
    float oacc[4][8];
#pragma unroll
    for (int i = 0; i < 4; i++)
#pragma unroll
        for (int c = 0; c < 8; c++) oacc[i][c] = 0.f;

    const float scale = 0.088388347648318447f; // 1/sqrt(128)

    for (int kt = 0; kt <= qt; kt++) {
        __syncthreads();
        // Load K transposed + V row-major
        for (int e = t; e < 64 * 32; e += 256) {
            int row = e >> 5;
            int c4  = (e & 31) * 4;
            size_t gidx = base_bh + (size_t)(kt * 64 + row) * DD + c4;
            float4 kv4 = *(const float4*)(k + gidx);
            Kt[(c4 + 0) * QK_P + row] = kv4.x;
            Kt[(c4 + 1) * QK_P + row] = kv4.y;
            Kt[(c4 + 2) * QK_P + row] = kv4.z;
            Kt[(c4 + 3) * QK_P + row] = kv4.w;
            *(float4*)&Vs[row * V_P + c4] = *(const float4*)(v + gidx);
        }
        __syncthreads();

        // ---- scores: 4x4 per thread, conflict-free contiguous loads ----
        float sacc[4][4];
#pragma unroll
        for (int ii = 0; ii < 4; ii++)
#pragma unroll
            for (int jj = 0; jj < 4; jj++) sacc[ii][jj] = 0.f;

#pragma unroll 4
        for (int kk = 0; kk < HD; kk++) {
            float4 qv = *(const float4*)&Qt[kk * QK_P + i0];
            float4 kv = *(const float4*)&Kt[kk * QK_P + j0];
            float a[4] = {qv.x, qv.y, qv.z, qv.w};
            float bq[4] = {kv.x, kv.y, kv.z, kv.w};
#pragma unroll
            for (int ii = 0; ii < 4; ii++)
#pragma unroll
                for (int jj = 0; jj < 4; jj++)
                    sacc[ii][jj] += a[ii] * bq[jj];
        }
#pragma unroll
        for (int ii = 0; ii < 4; ii++) {
            int gi = q0 + i0 + ii;
            float4 sv;
            sv.x = (kt * 64 + j0 + 0 <= gi) ? sacc[ii][0] * scale : -1e30f;
            sv.y = (kt * 64 + j0 + 1 <= gi) ? sacc[ii][1] * scale : -1e30f;
            sv.z = (kt * 64 + j0 + 2 <= gi) ? sacc[ii][2] * scale : -1e30f;
            sv.w = (kt * 64 + j0 + 3 <= gi) ? sacc[ii][3] * scale : -1e30f;
            *(float4*)&Ss[(i0 + ii) * S_P + j0] = sv;
        }
        __syncthreads();

        // ---- online softmax (4 threads per row) ----
        float mt = -1e30f;
        for (int j = g; j < 64; j += 4)
            mt = fmaxf(mt, Ss[r * S_P + j]);
        mt = fmaxf(mt, __shfl_xor_sync(0xffffffffu, mt, 1));
        mt = fmaxf(mt, __shfl_xor_sync(0xffffffffu, mt, 2));

        float m_new  = fmaxf(m_run, mt);
        float factor = __expf(m_run - m_new);
        float lsum = 0.f;
        for (int j = g; j < 64; j += 4) {
            float p = __expf(Ss[r * S_P + j] - m_new);
            Ss[r * S_P + j] = p;
            lsum += p;
        }
        lsum += __shfl_xor_sync(0xffffffffu, lsum, 1);
        lsum += __shfl_xor_sync(0xffffffffu, lsum, 2);
        l_run = l_run * factor + lsum;
        m_run = m_new;
        if (g == 0) rowfac[r] = factor;
        __syncthreads();

        // ---- PV: 4x8 microtile (rows i0.., cols j0.. and 64+j0..) ----
#pragma unroll
        for (int i = 0; i < 4; i++) {
            float f = rowfac[i0 + i];
#pragma unroll
            for (int c = 0; c < 8; c++) oacc[i][c] *= f;
        }
#pragma unroll 2
        for (int j = 0; j < 64; j++) {
            float p0 = Ss[(i0 + 0) * S_P + j];
            float p1 = Ss[(i0 + 1) * S_P + j];
            float p2 = Ss[(i0 + 2) * S_P + j];
            float p3 = Ss[(i0 + 3) * S_P + j];
            float4 va = *(const float4*)&Vs[j * V_P + j0];
            float4 vb = *(const float4*)&Vs[j * V_P + 64 + j0];
            oacc[0][0] += p0 * va.x; oacc[0][1] += p0 * va.y;
            oacc[0][2] += p0 * va.z; oacc[0][3] += p0 * va.w;
            oacc[0][4] += p0 * vb.x; oacc[0][5] += p0 * vb.y;
            oacc[0][6] += p0 * vb.z; oacc[0][7] += p0 * vb.w;
            oacc[1][0] += p1 * va.x; oacc[1][1] += p1 * va.y;
            oacc[1][2] += p1 * va.z; oacc[1][3] += p1 * va.w;
            oacc[1][4] += p1 * vb.x; oacc[1][5] += p1 * vb.y;
            oacc[1][6] += p1 * vb.z; oacc[1][7] += p1 * vb.w;
            oacc[2][0] += p2 * va.x; oacc[2][1] += p2 * va.y;
            oacc[2][2] += p2 * va.z; oacc[2][3] += p2 * va.w;
            oacc[2][4] += p2 * vb.x; oacc[2][5] += p2 * vb.y;
            oacc[2][6] += p2 * vb.z; oacc[2][7] += p2 * vb.w;
            oacc[3][0] += p3 * va.x; oacc[3][1] += p3 * va.y;
            oacc[3][2] += p3 * va.z; oacc[3][3] += p3 * va.w;
            oacc[3][4] += p3 * vb.x; oacc[3][5] += p3 * vb.y;
            oacc[3][6] += p3 * vb.z; oacc[3][7] += p3 * vb.w;
        }
    }

    if (g == 0) rowl[r] = l_run;
    __syncthreads();

#pragma unroll
    for (int i = 0; i < 4; i++) {
        float inv_l = 1.f / rowl[i0 + i];
        float* orow = ctx + base_bh + (size_t)(q0 + i0 + i) * DD;
        float4 oa, ob;
        oa.x = oacc[i][0] * inv_l; oa.y = oacc[i][1] * inv_l;
        oa.z = oacc[i][2] * inv_l; oa.w = oacc[i][3] * inv_l;
        ob.x = oacc[i][4] * inv_l; ob.y = oacc[i][5] * inv_l;
        ob.z = oacc[i][6] * inv_l; ob.w = oacc[i][7] * inv_l;
        *(float4*)(orow + j0)      = oa;
        *(float4*)(orow + 64 + j0) = ob;
    }
}

// ---------------------------------------------------------------------------
// Launch
// ---------------------------------------------------------------------------
extern "C" void kernel_launch(void* const* d_in, const int* in_sizes, int n_in,
                              void* d_out, int out_size)
{
    const float* x    = (const float*)d_in[0];
    const float* wq   = (const float*)d_in[1];
    const float* wdkv = (const float*)d_in[2];
    const float* wuk  = (const float*)d_in[3];
    const float* wuv  = (const float*)d_in[4];
    const float* wo   = (const float*)d_in[5];
    const float* bo   = (const float*)d_in[6];
    float* out = (float*)d_out;

    float *qb, *kb, *vb, *ctxb, *latb;
    cudaGetSymbolAddress((void**)&qb,   g_q);
    cudaGetSymbolAddress((void**)&kb,   g_k);
    cudaGetSymbolAddress((void**)&vb,   g_v);
    cudaGetSymbolAddress((void**)&ctxb, g_ctx);
    cudaGetSymbolAddress((void**)&latb, g_latent);

    cudaFuncSetAttribute(flash_kernel,
                         cudaFuncAttributeMaxDynamicSharedMemorySize,
                         FA_SMEM_BYTES);

    // latent = x @ wdkv^T   [4096 x 256]  (small-N kernel: 256 blocks)
    sgemm_nt64_kernel<<<dim3(LL / 64, MROWS / 64), 256>>>(
        x, wdkv, latb, MROWS, LL, DD);
    // q = x @ wq^T          [4096 x 2048]
    sgemm_nt_kernel<<<dim3(DD / 128, MROWS / 128), 256>>>(
        x, wq, nullptr, qb, MROWS, DD, DD);
    // k = latent @ wuk^T
    sgemm_nt_kernel<<<dim3(DD / 128, MROWS / 128), 256>>>(
        latb, wuk, nullptr, kb, MROWS, DD, LL);
    // v = latent @ wuv^T
    sgemm_nt_kernel<<<dim3(DD / 128, MROWS / 128), 256>>>(
        latb, wuv, nullptr, vb, MROWS, DD, LL);

    // RoPE on q, k in place
    {
        int total = MROWS * HH * 64;
        rope_kernel<<<(total + 255) / 256, 256>>>(qb, kb);
    }

    // flash attention -> ctx
    flash_kernel<<<dim3(SS / 64, HH, BB), 256, FA_SMEM_BYTES>>>(qb, kb, vb, ctxb);

    // out = ctx @ wo^T + bo
    sgemm_nt_kernel<<<dim3(DD / 128, MROWS / 128), 256>>>(
        ctxb, wo, bo, out, MROWS, DD, DD);
}

// round 4
// speedup vs baseline: 2.8562x; 1.3153x over previous
#include <cuda_runtime.h>
#include <cuda_bf16.h>
#include <math.h>
#include <stdint.h>

// Problem constants: B=2, S=2048, D=2048, L=256, H=16, hd=128
#define BB   2
#define SS   2048
#define DD   2048
#define LL   256
#define HH   16
#define HD   128
#define MROWS (BB * SS)

// ---------------------------------------------------------------------------
// Scratch
// ---------------------------------------------------------------------------
__device__ float g_q[(size_t)MROWS * DD];
__device__ float g_k[(size_t)MROWS * DD];
__device__ float g_v[(size_t)MROWS * DD];
__device__ float g_ctx[(size_t)MROWS * DD];
__device__ float g_latent[(size_t)MROWS * LL];

__device__ __nv_bfloat16 g_x_hi[(size_t)MROWS * DD];
__device__ __nv_bfloat16 g_x_lo[(size_t)MROWS * DD];
__device__ __nv_bfloat16 g_wq_hi[(size_t)DD * DD];
__device__ __nv_bfloat16 g_wq_lo[(size_t)DD * DD];
__device__ __nv_bfloat16 g_wdkv_hi[(size_t)LL * DD];
__device__ __nv_bfloat16 g_wdkv_lo[(size_t)LL * DD];
__device__ __nv_bfloat16 g_wuk_hi[(size_t)DD * LL];
__device__ __nv_bfloat16 g_wuk_lo[(size_t)DD * LL];
__device__ __nv_bfloat16 g_wuv_hi[(size_t)DD * LL];
__device__ __nv_bfloat16 g_wuv_lo[(size_t)DD * LL];
__device__ __nv_bfloat16 g_wo_hi[(size_t)DD * DD];
__device__ __nv_bfloat16 g_wo_lo[(size_t)DD * DD];
__device__ __nv_bfloat16 g_lat_hi[(size_t)MROWS * LL];
__device__ __nv_bfloat16 g_lat_lo[(size_t)MROWS * LL];
__device__ __nv_bfloat16 g_ctx_hi[(size_t)MROWS * DD];
__device__ __nv_bfloat16 g_ctx_lo[(size_t)MROWS * DD];

// ---------------------------------------------------------------------------
// Split fp32 -> bf16 hi + lo planes.
// ---------------------------------------------------------------------------
__global__ __launch_bounds__(256) void split_kernel(
    const float* __restrict__ src, __nv_bfloat16* __restrict__ hi,
    __nv_bfloat16* __restrict__ lo, int n4)
{
    int i = blockIdx.x * blockDim.x + threadIdx.x;
    if (i >= n4) return;
    float4 v = ((const float4*)src)[i];
    float vv[4];
    vv[0] = v.x; vv[1] = v.y; vv[2] = v.z; vv[3] = v.w;
    __nv_bfloat16 h[4];
    __nv_bfloat16 l[4];
#pragma unroll
    for (int c = 0; c < 4; c++) {
        h[c] = __float2bfloat16(vv[c]);
        l[c] = __float2bfloat16(vv[c] - __bfloat162float(h[c]));
    }
    *(uint2*)(hi + (size_t)i * 4) = *(uint2*)h;
    *(uint2*)(lo + (size_t)i * 4) = *(uint2*)l;
}

// ---------------------------------------------------------------------------
// HMMA helpers
// ---------------------------------------------------------------------------
__device__ __forceinline__ uint32_t su32(const void* p) {
    return (uint32_t)__cvta_generic_to_shared(p);
}
__device__ __forceinline__ void ldsm4(uint32_t* r, uint32_t a) {
    asm volatile("ldmatrix.sync.aligned.m8n8.x4.shared.b16 {%0,%1,%2,%3},[%4];"
                 : "=r"(r[0]), "=r"(r[1]), "=r"(r[2]), "=r"(r[3]) : "r"(a));
}
__device__ __forceinline__ void mma16816(float* d, const uint32_t* a,
                                         const uint32_t* b) {
    asm volatile(
        "mma.sync.aligned.m16n8k16.row.col.f32.bf16.bf16.f32 "
        "{%0,%1,%2,%3},{%4,%5,%6,%7},{%8,%9},{%0,%1,%2,%3};"
        : "+f"(d[0]), "+f"(d[1]), "+f"(d[2]), "+f"(d[3])
        : "r"(a[0]), "r"(a[1]), "r"(a[2]), "r"(a[3]), "r"(b[0]), "r"(b[1]));
}

// ---------------------------------------------------------------------------
// Split-bf16 GEMM: C[M,N] = A[M,K] @ B[N,K]^T (+bias), fp32 accumulate.
// 128x128x32 tile, 8 warps (2x4), warp tile 64x32. Terms: hh + hl + lh.
// ---------------------------------------------------------------------------
#define GP 40   // smem pitch in bf16 (80B rows): conflict-free ldmatrix

__global__ __launch_bounds__(256) void hgemm_split_nt(
    const __nv_bfloat16* __restrict__ Ahi, const __nv_bfloat16* __restrict__ Alo,
    const __nv_bfloat16* __restrict__ Bhi, const __nv_bfloat16* __restrict__ Blo,
    const float* __restrict__ bias, float* __restrict__ C,
    int M, int N, int K)
{
    __shared__ __nv_bfloat16 sAh[128 * GP];
    __shared__ __nv_bfloat16 sAl[128 * GP];
    __shared__ __nv_bfloat16 sBh[128 * GP];
    __shared__ __nv_bfloat16 sBl[128 * GP];

    const int t    = threadIdx.x;
    const int lane = t & 31;
    const int warp = t >> 5;
    const int wm   = warp >> 2;
    const int wn   = warp & 3;
    const int row0 = blockIdx.y * 128;
    const int col0 = blockIdx.x * 128;

    const int lrow = t >> 1;
    const int lk   = (t & 1) * 16;
    const __nv_bfloat16* pAh = Ahi + (size_t)(row0 + lrow) * K + lk;
    const __nv_bfloat16* pAl = Alo + (size_t)(row0 + lrow) * K + lk;
    const __nv_bfloat16* pBh = Bhi + (size_t)(col0 + lrow) * K + lk;
    const __nv_bfloat16* pBl = Blo + (size_t)(col0 + lrow) * K + lk;

    float acc[4][4][4];
#pragma unroll
    for (int i = 0; i < 4; i++)
#pragma unroll
        for (int j = 0; j < 4; j++)
#pragma unroll
            for (int c = 0; c < 4; c++) acc[i][j][c] = 0.f;

    uint4 rah0, rah1, ral0, ral1, rbh0, rbh1, rbl0, rbl1;
    rah0 = *(const uint4*)(pAh);     rah1 = *(const uint4*)(pAh + 8);
    ral0 = *(const uint4*)(pAl);     ral1 = *(const uint4*)(pAl + 8);
    rbh0 = *(const uint4*)(pBh);     rbh1 = *(const uint4*)(pBh + 8);
    rbl0 = *(const uint4*)(pBl);     rbl1 = *(const uint4*)(pBl + 8);

    const int soff = lrow * GP + lk;
    const int nkt = K / 32;

    const int lm_r = (lane & 7) + ((lane >> 3) & 1) * 8;
    const int lm_c = (lane >> 4) * 8;

    for (int kt = 0; kt < nkt; kt++) {
        __syncthreads();
        *(uint4*)(sAh + soff) = rah0; *(uint4*)(sAh + soff + 8) = rah1;
        *(uint4*)(sAl + soff) = ral0; *(uint4*)(sAl + soff + 8) = ral1;
        *(uint4*)(sBh + soff) = rbh0; *(uint4*)(sBh + soff + 8) = rbh1;
        *(uint4*)(sBl + soff) = rbl0; *(uint4*)(sBl + soff + 8) = rbl1;
        __syncthreads();

        if (kt + 1 < nkt) {
            int adv = (kt + 1) * 32;
            rah0 = *(const uint4*)(pAh + adv); rah1 = *(const uint4*)(pAh + adv + 8);
            ral0 = *(const uint4*)(pAl + adv); ral1 = *(const uint4*)(pAl + adv + 8);
            rbh0 = *(const uint4*)(pBh + adv); rbh1 = *(const uint4*)(pBh + adv + 8);
            rbl0 = *(const uint4*)(pBl + adv); rbl1 = *(const uint4*)(pBl + adv + 8);
        }

#pragma unroll
        for (int kc = 0; kc < 2; kc++) {
            const int c0 = kc * 16 + lm_c;
            uint32_t ah[4][4];
            uint32_t al[4][4];
            uint32_t bh[4][2];
            uint32_t bl[4][2];
#pragma unroll
            for (int mt = 0; mt < 4; mt++) {
                int r = wm * 64 + mt * 16 + lm_r;
                ldsm4(ah[mt], su32(sAh + r * GP + c0));
                ldsm4(al[mt], su32(sAl + r * GP + c0));
            }
#pragma unroll
            for (int np = 0; np < 2; np++) {
                int r = wn * 32 + np * 16 + lm_r;
                uint32_t tmp[4];
                ldsm4(tmp, su32(sBh + r * GP + c0));
                bh[2 * np][0]     = tmp[0]; bh[2 * np][1]     = tmp[2];
                bh[2 * np + 1][0] = tmp[1]; bh[2 * np + 1][1] = tmp[3];
                ldsm4(tmp, su32(sBl + r * GP + c0));
                bl[2 * np][0]     = tmp[0]; bl[2 * np][1]     = tmp[2];
                bl[2 * np + 1][0] = tmp[1]; bl[2 * np + 1][1] = tmp[3];
            }
#pragma unroll
            for (int mt = 0; mt < 4; mt++) {
#pragma unroll
                for (int nt = 0; nt < 4; nt++) {
                    mma16816(acc[mt][nt], ah[mt], bh[nt]);
                    mma16816(acc[mt][nt], ah[mt], bl[nt]);
                    mma16816(acc[mt][nt], al[mt], bh[nt]);
                }
            }
        }
    }

#pragma unroll
    for (int mt = 0; mt < 4; mt++) {
#pragma unroll
        for (int nt = 0; nt < 4; nt++) {
            int gr = row0 + wm * 64 + mt * 16 + (lane >> 2);
            int gc = col0 + wn * 32 + nt * 8 + (lane & 3) * 2;
            float b0 = 0.f;
            float b1 = 0.f;
            if (bias) { b0 = bias[gc]; b1 = bias[gc + 1]; }
            float2 o0;
            float2 o1;
            o0.x = acc[mt][nt][0] + b0; o0.y = acc[mt][nt][1] + b1;
            o1.x = acc[mt][nt][2] + b0; o1.y = acc[mt][nt][3] + b1;
            *(float2*)(C + (size_t)gr * N + gc)       = o0;
            *(float2*)(C + (size_t)(gr + 8) * N + gc) = o1;
        }
    }
}

// ---------------------------------------------------------------------------
// RoPE in-place on q and k.
// ---------------------------------------------------------------------------
__global__ __launch_bounds__(256) void rope_kernel(float* __restrict__ q,
                                                   float* __restrict__ k)
{
    int idx = blockIdx.x * blockDim.x + threadIdx.x;
    const int total = MROWS * HH * 64;
    if (idx >= total) return;

    int j   = idx & 63;
    int h   = (idx >> 6) & (HH - 1);
    int row = idx >> 10;
    int s   = row & (SS - 1);

    const float LOG2_BASE = 13.287712379549449f;
    float inv = exp2f(-(float)j * (LOG2_BASE / 64.0f));
    float ang = (float)s * inv;
    float c, sn;
    sincosf(ang, &sn, &c);

    size_t base = (size_t)row * DD + h * HD;

    float q1 = q[base + j];
    float q2 = q[base + j + 64];
    q[base + j]      = q1 * c - q2 * sn;
    q[base + j + 64] = q2 * c + q1 * sn;

    float k1 = k[base + j];
    float k2 = k[base + j + 64];
    k[base + j]      = k1 * c - k2 * sn;
    k[base + j + 64] = k2 * c + k1 * sn;
}

// ---------------------------------------------------------------------------
// Causal flash attention, fp32 FMA (R2 design, PV loop compacted).
// ---------------------------------------------------------------------------
#define QK_P 68
#define V_P  132
#define S_P  68
#define FA_SMEM_FLOATS (2 * 128 * QK_P + 64 * V_P + 64 * S_P + 128)
#define FA_SMEM_BYTES  (FA_SMEM_FLOATS * 4)

__global__ __launch_bounds__(256) void flash_kernel(
    const float* __restrict__ q, const float* __restrict__ k,
    const float* __restrict__ v, float* __restrict__ ctx)
{
    extern __shared__ float smf[];
    float* Qt = smf;
    float* Kt = Qt + 128 * QK_P;
    float* Vs = Kt + 128 * QK_P;
    float* Ss = Vs + 64 * V_P;
    float* rowfac = Ss + 64 * S_P;
    float* rowl   = rowfac + 64;

    const int qt = blockIdx.x;
    const int h  = blockIdx.y;
    const int b  = blockIdx.z;
    const int t  = threadIdx.x;

    const int q0 = qt * 64;
    const size_t base_bh = (size_t)b * SS * DD + (size_t)h * HD;

    for (int e = t; e < 64 * 32; e += 256) {
        int row = e >> 5;
        int c4  = (e & 31) * 4;
        float4 val = *(const float4*)(q + base_bh + (size_t)(q0 + row) * DD + c4);
        Qt[(c4 + 0) * QK_P + row] = val.x;
        Qt[(c4 + 1) * QK_P + row] = val.y;
        Qt[(c4 + 2) * QK_P + row] = val.z;
        Qt[(c4 + 3) * QK_P + row] = val.w;
    }

    const int ty = t >> 4;
    const int tx = t & 15;
    const int i0 = ty * 4;
    const int j0 = tx * 4;
    const int r  = t >> 2;
    const int g  = t & 3;

    float m_run = -1e30f;
    float l_run = 0.f;
    float oacc[4][8];
#pragma unroll
    for (int i = 0; i < 4; i++)
#pragma unroll
        for (int c = 0; c < 8; c++) oacc[i][c] = 0.f;

    const float scale = 0.088388347648318447f;

    for (int kt = 0; kt <= qt; kt++) {
        __syncthreads();
        for (int e = t; e < 64 * 32; e += 256) {
            int row = e >> 5;
            int c4  = (e & 31) * 4;
            size_t gidx = base_bh + (size_t)(kt * 64 + row) * DD + c4;
            float4 kv4 = *(const float4*)(k + gidx);
            Kt[(c4 + 0) * QK_P + row] = kv4.x;
            Kt[(c4 + 1) * QK_P + row] = kv4.y;
            Kt[(c4 + 2) * QK_P + row] = kv4.z;
            Kt[(c4 + 3) * QK_P + row] = kv4.w;
            *(float4*)(Vs + row * V_P + c4) = *(const float4*)(v + gidx);
        }
        __syncthreads();

        float sacc[4][4];
#pragma unroll
        for (int ii = 0; ii < 4; ii++)
#pragma unroll
            for (int jj = 0; jj < 4; jj++) sacc[ii][jj] = 0.f;

#pragma unroll 4
        for (int kk = 0; kk < HD; kk++) {
            float4 qv = *(const float4*)(Qt + kk * QK_P + i0);
            float4 kv = *(const float4*)(Kt + kk * QK_P + j0);
            float aa[4];
            float bb[4];
            aa[0] = qv.x; aa[1] = qv.y; aa[2] = qv.z; aa[3] = qv.w;
            bb[0] = kv.x; bb[1] = kv.y; bb[2] = kv.z; bb[3] = kv.w;
#pragma unroll
            for (int ii = 0; ii < 4; ii++)
#pragma unroll
                for (int jj = 0; jj < 4; jj++)
                    sacc[ii][jj] += aa[ii] * bb[jj];
        }

#pragma unroll
        for (int ii = 0; ii < 4; ii++) {
            int gi = q0 + i0 + ii;
            float sv[4];
#pragma unroll
            for (int jj = 0; jj < 4; jj++) {
                int gj = kt * 64 + j0 + jj;
                sv[jj] = (gj <= gi) ? sacc[ii][jj] * scale : -1e30f;
            }
            float4 svv;
            svv.x = sv[0]; svv.y = sv[1]; svv.z = sv[2]; svv.w = sv[3];
            *(float4*)(Ss + (i0 + ii) * S_P + j0) = svv;
        }
        __syncthreads();

        float mt = -1e30f;
        for (int j = g; j < 64; j += 4)
            mt = fmaxf(mt, Ss[r * S_P + j]);
        mt = fmaxf(mt, __shfl_xor_sync(0xffffffffu, mt, 1));
        mt = fmaxf(mt, __shfl_xor_sync(0xffffffffu, mt, 2));

        float m_new  = fmaxf(m_run, mt);
        float factor = __expf(m_run - m_new);
        float lsum = 0.f;
        for (int j = g; j < 64; j += 4) {
            float p = __expf(Ss[r * S_P + j] - m_new);
            Ss[r * S_P + j] = p;
            lsum += p;
        }
        lsum += __shfl_xor_sync(0xffffffffu, lsum, 1);
        lsum += __shfl_xor_sync(0xffffffffu, lsum, 2);
        l_run = l_run * factor + lsum;
        m_run = m_new;
        if (g == 0) rowfac[r] = factor;
        __syncthreads();

#pragma unroll
        for (int i = 0; i < 4; i++) {
            float f = rowfac[i0 + i];
#pragma unroll
            for (int c = 0; c < 8; c++) oacc[i][c] *= f;
        }

#pragma unroll 2
        for (int j = 0; j < 64; j++) {
            float4 va = *(const float4*)(Vs + j * V_P + j0);
            float4 wv = *(const float4*)(Vs + j * V_P + 64 + j0);
            float vv[8];
            vv[0] = va.x; vv[1] = va.y; vv[2] = va.z; vv[3] = va.w;
            vv[4] = wv.x; vv[5] = wv.y; vv[6] = wv.z; vv[7] = wv.w;
#pragma unroll
            for (int i = 0; i < 4; i++) {
                float p = Ss[(i0 + i) * S_P + j];
#pragma unroll
                for (int c = 0; c < 8; c++) oacc[i][c] += p * vv[c];
            }
        }
    }

    if (g == 0) rowl[r] = l_run;
    __syncthreads();

#pragma unroll
    for (int i = 0; i < 4; i++) {
        float inv_l = 1.f / rowl[i0 + i];
        float* orow = ctx + base_bh + (size_t)(q0 + i0 + i) * DD;
        float4 oa;
        float4 ob;
        oa.x = oacc[i][0] * inv_l; oa.y = oacc[i][1] * inv_l;
        oa.z = oacc[i][2] * inv_l; oa.w = oacc[i][3] * inv_l;
        ob.x = oacc[i][4] * inv_l; ob.y = oacc[i][5] * inv_l;
        ob.z = oacc[i][6] * inv_l; ob.w = oacc[i][7] * inv_l;
        *(float4*)(orow + j0)      = oa;
        *(float4*)(orow + 64 + j0) = ob;
    }
}

// ---------------------------------------------------------------------------
// Launch
// ---------------------------------------------------------------------------
static void split_launch(const float* src, __nv_bfloat16* hi,
                         __nv_bfloat16* lo, size_t n)
{
    int n4 = (int)(n / 4);
    split_kernel<<<(n4 + 255) / 256, 256>>>(src, hi, lo, n4);
}

extern "C" void kernel_launch(void* const* d_in, const int* in_sizes, int n_in,
                              void* d_out, int out_size)
{
    const float* x    = (const float*)d_in[0];
    const float* wq   = (const float*)d_in[1];
    const float* wdkv = (const float*)d_in[2];
    const float* wuk  = (const float*)d_in[3];
    const float* wuv  = (const float*)d_in[4];
    const float* wo   = (const float*)d_in[5];
    const float* bo   = (const float*)d_in[6];
    float* out = (float*)d_out;

    float *qb, *kb, *vb, *ctxb, *latb;
    cudaGetSymbolAddress((void**)&qb,   g_q);
    cudaGetSymbolAddress((void**)&kb,   g_k);
    cudaGetSymbolAddress((void**)&vb,   g_v);
    cudaGetSymbolAddress((void**)&ctxb, g_ctx);
    cudaGetSymbolAddress((void**)&latb, g_latent);

    __nv_bfloat16 *xh, *xl, *wqh, *wql, *wdh, *wdl, *wukh, *wukl;
    __nv_bfloat16 *wuvh, *wuvl, *woh, *wol, *lath, *latl, *ctxh, *ctxl;
    cudaGetSymbolAddress((void**)&xh,   g_x_hi);
    cudaGetSymbolAddress((void**)&xl,   g_x_lo);
    cudaGetSymbolAddress((void**)&wqh,  g_wq_hi);
    cudaGetSymbolAddress((void**)&wql,  g_wq_lo);
    cudaGetSymbolAddress((void**)&wdh,  g_wdkv_hi);
    cudaGetSymbolAddress((void**)&wdl,  g_wdkv_lo);
    cudaGetSymbolAddress((void**)&wukh, g_wuk_hi);
    cudaGetSymbolAddress((void**)&wukl, g_wuk_lo);
    cudaGetSymbolAddress((void**)&wuvh, g_wuv_hi);
    cudaGetSymbolAddress((void**)&wuvl, g_wuv_lo);
    cudaGetSymbolAddress((void**)&woh,  g_wo_hi);
    cudaGetSymbolAddress((void**)&wol,  g_wo_lo);
    cudaGetSymbolAddress((void**)&lath, g_lat_hi);
    cudaGetSymbolAddress((void**)&latl, g_lat_lo);
    cudaGetSymbolAddress((void**)&ctxh, g_ctx_hi);
    cudaGetSymbolAddress((void**)&ctxl, g_ctx_lo);

    cudaFuncSetAttribute(flash_kernel,
                         cudaFuncAttributeMaxDynamicSharedMemorySize,
                         FA_SMEM_BYTES);

    split_launch(x,    xh,   xl,   (size_t)MROWS * DD);
    split_launch(wq,   wqh,  wql,  (size_t)DD * DD);
    split_launch(wdkv, wdh,  wdl,  (size_t)LL * DD);
    split_launch(wuk,  wukh, wukl, (size_t)DD * LL);
    split_launch(wuv,  wuvh, wuvl, (size_t)DD * LL);
    split_launch(wo,   woh,  wol,  (size_t)DD * DD);

    // latent = x @ wdkv^T
    hgemm_split_nt<<<dim3(LL / 128, MROWS / 128), 256>>>(
        xh, xl, wdh, wdl, (const float*)0, latb, MROWS, LL, DD);
    split_launch(latb, lath, latl, (size_t)MROWS * LL);

    // q = x @ wq^T
    hgemm_split_nt<<<dim3(DD / 128, MROWS / 128), 256>>>(
        xh, xl, wqh, wql, (const float*)0, qb, MROWS, DD, DD);
    // k = latent @ wuk^T
    hgemm_split_nt<<<dim3(DD / 128, MROWS / 128), 256>>>(
        lath, latl, wukh, wukl, (const float*)0, kb, MROWS, DD, LL);
    // v = latent @ wuv^T
    hgemm_split_nt<<<dim3(DD / 128, MROWS / 128), 256>>>(
        lath, latl, wuvh, wuvl, (const float*)0, vb, MROWS, DD, LL);

    // RoPE
    {
        int total = MROWS * HH * 64;
        rope_kernel<<<(total + 255) / 256, 256>>>(qb, kb);
    }

    // flash attention -> ctx
    flash_kernel<<<dim3(SS / 64, HH, BB), 256, FA_SMEM_BYTES>>>(qb, kb, vb, ctxb);

    // out = ctx @ wo^T + bo
    split_launch(ctxb, ctxh, ctxl, (size_t)MROWS * DD);
    hgemm_split_nt<<<dim3(DD / 128, MROWS / 128), 256>>>(
        ctxh, ctxl, woh, wol, bo, out, MROWS, DD, DD);
}

// round 5
// speedup vs baseline: 3.0429x; 1.0654x over previous
#include <cuda_runtime.h>
#include <cuda_bf16.h>
#include <math.h>
#include <stdint.h>

// Problem constants: B=2, S=2048, D=2048, L=256, H=16, hd=128
#define BB   2
#define SS   2048
#define DD   2048
#define LL   256
#define HH   16
#define HD   128
#define MROWS (BB * SS)

// ---------------------------------------------------------------------------
// Scratch
// ---------------------------------------------------------------------------
__device__ float g_q[(size_t)MROWS * DD];
__device__ float g_k[(size_t)MROWS * DD];
__device__ float g_v[(size_t)MROWS * DD];
__device__ float g_ctx[(size_t)MROWS * DD];
__device__ float g_latent[(size_t)MROWS * LL];

__device__ __nv_bfloat16 g_x_hi[(size_t)MROWS * DD];
__device__ __nv_bfloat16 g_x_lo[(size_t)MROWS * DD];
__device__ __nv_bfloat16 g_wq_hi[(size_t)DD * DD];
__device__ __nv_bfloat16 g_wq_lo[(size_t)DD * DD];
__device__ __nv_bfloat16 g_wdkv_hi[(size_t)LL * DD];
__device__ __nv_bfloat16 g_wdkv_lo[(size_t)LL * DD];
__device__ __nv_bfloat16 g_wuk_hi[(size_t)DD * LL];
__device__ __nv_bfloat16 g_wuk_lo[(size_t)DD * LL];
__device__ __nv_bfloat16 g_wuv_hi[(size_t)DD * LL];
__device__ __nv_bfloat16 g_wuv_lo[(size_t)DD * LL];
__device__ __nv_bfloat16 g_wo_hi[(size_t)DD * DD];
__device__ __nv_bfloat16 g_wo_lo[(size_t)DD * DD];
__device__ __nv_bfloat16 g_lat_hi[(size_t)MROWS * LL];
__device__ __nv_bfloat16 g_lat_lo[(size_t)MROWS * LL];
__device__ __nv_bfloat16 g_ctx_hi[(size_t)MROWS * DD];
__device__ __nv_bfloat16 g_ctx_lo[(size_t)MROWS * DD];

// ---------------------------------------------------------------------------
// Split fp32 -> bf16 hi + lo planes.
// ---------------------------------------------------------------------------
__global__ __launch_bounds__(256) void split_kernel(
    const float* __restrict__ src, __nv_bfloat16* __restrict__ hi,
    __nv_bfloat16* __restrict__ lo, int n4)
{
    int i = blockIdx.x * blockDim.x + threadIdx.x;
    if (i >= n4) return;
    float4 v = ((const float4*)src)[i];
    float vv[4];
    vv[0] = v.x; vv[1] = v.y; vv[2] = v.z; vv[3] = v.w;
    __nv_bfloat16 h[4];
    __nv_bfloat16 l[4];
#pragma unroll
    for (int c = 0; c < 4; c++) {
        h[c] = __float2bfloat16(vv[c]);
        l[c] = __float2bfloat16(vv[c] - __bfloat162float(h[c]));
    }
    *(uint2*)(hi + (size_t)i * 4) = *(uint2*)h;
    *(uint2*)(lo + (size_t)i * 4) = *(uint2*)l;
}

// ---------------------------------------------------------------------------
// HMMA / async helpers
// ---------------------------------------------------------------------------
__device__ __forceinline__ uint32_t su32(const void* p) {
    return (uint32_t)__cvta_generic_to_shared(p);
}
__device__ __forceinline__ void ldsm4(uint32_t* r, uint32_t a) {
    asm volatile("ldmatrix.sync.aligned.m8n8.x4.shared.b16 {%0,%1,%2,%3},[%4];"
                 : "=r"(r[0]), "=r"(r[1]), "=r"(r[2]), "=r"(r[3]) : "r"(a));
}
__device__ __forceinline__ void mma16816(float* d, const uint32_t* a,
                                         const uint32_t* b) {
    asm volatile(
        "mma.sync.aligned.m16n8k16.row.col.f32.bf16.bf16.f32 "
        "{%0,%1,%2,%3},{%4,%5,%6,%7},{%8,%9},{%0,%1,%2,%3};"
        : "+f"(d[0]), "+f"(d[1]), "+f"(d[2]), "+f"(d[3])
        : "r"(a[0]), "r"(a[1]), "r"(a[2]), "r"(a[3]), "r"(b[0]), "r"(b[1]));
}
__device__ __forceinline__ void cpa16(uint32_t saddr, const void* g) {
    asm volatile("cp.async.ca.shared.global [%0],[%1],16;"
                 :: "r"(saddr), "l"(g));
}
__device__ __forceinline__ void cp_commit() {
    asm volatile("cp.async.commit_group;");
}
template <int N>
__device__ __forceinline__ void cp_wait() {
    asm volatile("cp.async.wait_group %0;" :: "n"(N));
}

// ---------------------------------------------------------------------------
// Split-bf16 GEMM, 3-stage cp.async pipeline.
// C[M,N] = A[M,K] @ B[N,K]^T (+bias), fp32 accumulate.
// 128x128x32 tile, 8 warps (2x4), warp tile 64x32. Terms: hh + hl + lh.
// ---------------------------------------------------------------------------
#define GP 40                       // smem pitch (bf16): conflict-free ldmatrix
#define PLANE (128 * GP)            // elems per plane
#define STAGES 3
#define GEMM_SMEM_BYTES (STAGES * 4 * PLANE * 2)

__global__ __launch_bounds__(256) void hgemm_split_nt(
    const __nv_bfloat16* __restrict__ Ahi, const __nv_bfloat16* __restrict__ Alo,
    const __nv_bfloat16* __restrict__ Bhi, const __nv_bfloat16* __restrict__ Blo,
    const float* __restrict__ bias, float* __restrict__ C,
    int M, int N, int K)
{
    extern __shared__ __nv_bfloat16 smg[];

    const int t    = threadIdx.x;
    const int lane = t & 31;
    const int warp = t >> 5;
    const int wm   = warp >> 2;
    const int wn   = warp & 3;
    const int row0 = blockIdx.y * 128;
    const int col0 = blockIdx.x * 128;

    const int lrow = t >> 1;
    const int lk   = (t & 1) * 16;
    const __nv_bfloat16* pAh = Ahi + (size_t)(row0 + lrow) * K + lk;
    const __nv_bfloat16* pAl = Alo + (size_t)(row0 + lrow) * K + lk;
    const __nv_bfloat16* pBh = Bhi + (size_t)(col0 + lrow) * K + lk;
    const __nv_bfloat16* pBl = Blo + (size_t)(col0 + lrow) * K + lk;

    const int soff = lrow * GP + lk;
    const uint32_t smem_base = su32(smg);
    const int nkt = K / 32;

    float acc[4][4][4];
#pragma unroll
    for (int i = 0; i < 4; i++)
#pragma unroll
        for (int j = 0; j < 4; j++)
#pragma unroll
            for (int c = 0; c < 4; c++) acc[i][j][c] = 0.f;

    // stage fill: 4 planes, 2x16B per plane per thread
#define FILL_STAGE(stg, ktv)                                                  \
    do {                                                                      \
        if ((ktv) < nkt) {                                                    \
            int adv = (ktv) * 32;                                             \
            uint32_t sb = smem_base + (uint32_t)(((stg) * 4) * PLANE + soff) * 2; \
            cpa16(sb,                    pAh + adv);                          \
            cpa16(sb + 16,               pAh + adv + 8);                      \
            cpa16(sb + PLANE * 2,        pAl + adv);                          \
            cpa16(sb + PLANE * 2 + 16,   pAl + adv + 8);                      \
            cpa16(sb + PLANE * 4,        pBh + adv);                          \
            cpa16(sb + PLANE * 4 + 16,   pBh + adv + 8);                      \
            cpa16(sb + PLANE * 6,        pBl + adv);                          \
            cpa16(sb + PLANE * 6 + 16,   pBl + adv + 8);                      \
        }                                                                     \
        cp_commit();                                                          \
    } while (0)

    // prologue: STAGES-1 stages in flight
    FILL_STAGE(0, 0);
    FILL_STAGE(1, 1);

    const int lm_r = (lane & 7) + ((lane >> 3) & 1) * 8;
    const int lm_c = (lane >> 4) * 8;

    for (int kt = 0; kt < nkt; kt++) {
        const int cur = kt % STAGES;
        cp_wait<STAGES - 2>();
        __syncthreads();

        // refill the stage consumed at kt-1 (safe: fully read before the
        // barrier above) with data kt+STAGES-1
        FILL_STAGE((kt + STAGES - 1) % STAGES, kt + STAGES - 1);

        const __nv_bfloat16* sAh = smg + (cur * 4 + 0) * PLANE;
        const __nv_bfloat16* sAl = smg + (cur * 4 + 1) * PLANE;
        const __nv_bfloat16* sBh = smg + (cur * 4 + 2) * PLANE;
        const __nv_bfloat16* sBl = smg + (cur * 4 + 3) * PLANE;

#pragma unroll
        for (int kc = 0; kc < 2; kc++) {
            const int c0 = kc * 16 + lm_c;
            uint32_t ah[4][4];
            uint32_t al[4][4];
            uint32_t bh[4][2];
            uint32_t bl[4][2];
#pragma unroll
            for (int mt = 0; mt < 4; mt++) {
                int r = wm * 64 + mt * 16 + lm_r;
                ldsm4(ah[mt], su32(sAh + r * GP + c0));
                ldsm4(al[mt], su32(sAl + r * GP + c0));
            }
#pragma unroll
            for (int np = 0; np < 2; np++) {
                int r = wn * 32 + np * 16 + lm_r;
                uint32_t tmp[4];
                ldsm4(tmp, su32(sBh + r * GP + c0));
                bh[2 * np][0]     = tmp[0]; bh[2 * np][1]     = tmp[2];
                bh[2 * np + 1][0] = tmp[1]; bh[2 * np + 1][1] = tmp[3];
                ldsm4(tmp, su32(sBl + r * GP + c0));
                bl[2 * np][0]     = tmp[0]; bl[2 * np][1]     = tmp[2];
                bl[2 * np + 1][0] = tmp[1]; bl[2 * np + 1][1] = tmp[3];
            }
#pragma unroll
            for (int mt = 0; mt < 4; mt++) {
#pragma unroll
                for (int nt = 0; nt < 4; nt++) {
                    mma16816(acc[mt][nt], ah[mt], bh[nt]);
                    mma16816(acc[mt][nt], ah[mt], bl[nt]);
                    mma16816(acc[mt][nt], al[mt], bh[nt]);
                }
            }
        }
        __syncthreads();
    }

#pragma unroll
    for (int mt = 0; mt < 4; mt++) {
#pragma unroll
        for (int nt = 0; nt < 4; nt++) {
            int gr = row0 + wm * 64 + mt * 16 + (lane >> 2);
            int gc = col0 + wn * 32 + nt * 8 + (lane & 3) * 2;
            float b0 = 0.f;
            float b1 = 0.f;
            if (bias) { b0 = bias[gc]; b1 = bias[gc + 1]; }
            float2 o0;
            float2 o1;
            o0.x = acc[mt][nt][0] + b0; o0.y = acc[mt][nt][1] + b1;
            o1.x = acc[mt][nt][2] + b0; o1.y = acc[mt][nt][3] + b1;
            *(float2*)(C + (size_t)gr * N + gc)       = o0;
            *(float2*)(C + (size_t)(gr + 8) * N + gc) = o1;
        }
    }
}

// ---------------------------------------------------------------------------
// RoPE in-place on q and k.
// ---------------------------------------------------------------------------
__global__ __launch_bounds__(256) void rope_kernel(float* __restrict__ q,
                                                   float* __restrict__ k)
{
    int idx = blockIdx.x * blockDim.x + threadIdx.x;
    const int total = MROWS * HH * 64;
    if (idx >= total) return;

    int j   = idx & 63;
    int h   = (idx >> 6) & (HH - 1);
    int row = idx >> 10;
    int s   = row & (SS - 1);

    const float LOG2_BASE = 13.287712379549449f;
    float inv = exp2f(-(float)j * (LOG2_BASE / 64.0f));
    float ang = (float)s * inv;
    float c, sn;
    sincosf(ang, &sn, &c);

    size_t base = (size_t)row * DD + h * HD;

    float q1 = q[base + j];
    float q2 = q[base + j + 64];
    q[base + j]      = q1 * c - q2 * sn;
    q[base + j + 64] = q2 * c + q1 * sn;

    float k1 = k[base + j];
    float k2 = k[base + j + 64];
    k[base + j]      = k1 * c - k2 * sn;
    k[base + j + 64] = k2 * c + k1 * sn;
}

// ---------------------------------------------------------------------------
// Causal flash attention, fp32 FMA (unchanged from R4).
// ---------------------------------------------------------------------------
#define QK_P 68
#define V_P  132
#define S_P  68
#define FA_SMEM_FLOATS (2 * 128 * QK_P + 64 * V_P + 64 * S_P + 128)
#define FA_SMEM_BYTES  (FA_SMEM_FLOATS * 4)

__global__ __launch_bounds__(256) void flash_kernel(
    const float* __restrict__ q, const float* __restrict__ k,
    const float* __restrict__ v, float* __restrict__ ctx)
{
    extern __shared__ float smf[];
    float* Qt = smf;
    float* Kt = Qt + 128 * QK_P;
    float* Vs = Kt + 128 * QK_P;
    float* Ss = Vs + 64 * V_P;
    float* rowfac = Ss + 64 * S_P;
    float* rowl   = rowfac + 64;

    const int qt = blockIdx.x;
    const int h  = blockIdx.y;
    const int b  = blockIdx.z;
    const int t  = threadIdx.x;

    const int q0 = qt * 64;
    const size_t base_bh = (size_t)b * SS * DD + (size_t)h * HD;

    for (int e = t; e < 64 * 32; e += 256) {
        int row = e >> 5;
        int c4  = (e & 31) * 4;
        float4 val = *(const float4*)(q + base_bh + (size_t)(q0 + row) * DD + c4);
        Qt[(c4 + 0) * QK_P + row] = val.x;
        Qt[(c4 + 1) * QK_P + row] = val.y;
        Qt[(c4 + 2) * QK_P + row] = val.z;
        Qt[(c4 + 3) * QK_P + row] = val.w;
    }

    const int ty = t >> 4;
    const int tx = t & 15;
    const int i0 = ty * 4;
    const int j0 = tx * 4;
    const int r  = t >> 2;
    const int g  = t & 3;

    float m_run = -1e30f;
    float l_run = 0.f;
    float oacc[4][8];
#pragma unroll
    for (int i = 0; i < 4; i++)
#pragma unroll
        for (int c = 0; c < 8; c++) oacc[i][c] = 0.f;

    const float scale = 0.088388347648318447f;

    for (int kt = 0; kt <= qt; kt++) {
        __syncthreads();
        for (int e = t; e < 64 * 32; e += 256) {
            int row = e >> 5;
            int c4  = (e & 31) * 4;
            size_t gidx = base_bh + (size_t)(kt * 64 + row) * DD + c4;
            float4 kv4 = *(const float4*)(k + gidx);
            Kt[(c4 + 0) * QK_P + row] = kv4.x;
            Kt[(c4 + 1) * QK_P + row] = kv4.y;
            Kt[(c4 + 2) * QK_P + row] = kv4.z;
            Kt[(c4 + 3) * QK_P + row] = kv4.w;
            *(float4*)(Vs + row * V_P + c4) = *(const float4*)(v + gidx);
        }
        __syncthreads();

        float sacc[4][4];
#pragma unroll
        for (int ii = 0; ii < 4; ii++)
#pragma unroll
            for (int jj = 0; jj < 4; jj++) sacc[ii][jj] = 0.f;

#pragma unroll 4
        for (int kk = 0; kk < HD; kk++) {
            float4 qv = *(const float4*)(Qt + kk * QK_P + i0);
            float4 kv = *(const float4*)(Kt + kk * QK_P + j0);
            float aa[4];
            float bb[4];
            aa[0] = qv.x; aa[1] = qv.y; aa[2] = qv.z; aa[3] = qv.w;
            bb[0] = kv.x; bb[1] = kv.y; bb[2] = kv.z; bb[3] = kv.w;
#pragma unroll
            for (int ii = 0; ii < 4; ii++)
#pragma unroll
                for (int jj = 0; jj < 4; jj++)
                    sacc[ii][jj] += aa[ii] * bb[jj];
        }

#pragma unroll
        for (int ii = 0; ii < 4; ii++) {
            int gi = q0 + i0 + ii;
            float sv[4];
#pragma unroll
            for (int jj = 0; jj < 4; jj++) {
                int gj = kt * 64 + j0 + jj;
                sv[jj] = (gj <= gi) ? sacc[ii][jj] * scale : -1e30f;
            }
            float4 svv;
            svv.x = sv[0]; svv.y = sv[1]; svv.z = sv[2]; svv.w = sv[3];
            *(float4*)(Ss + (i0 + ii) * S_P + j0) = svv;
        }
        __syncthreads();

        float mt = -1e30f;
        for (int j = g; j < 64; j += 4)
            mt = fmaxf(mt, Ss[r * S_P + j]);
        mt = fmaxf(mt, __shfl_xor_sync(0xffffffffu, mt, 1));
        mt = fmaxf(mt, __shfl_xor_sync(0xffffffffu, mt, 2));

        float m_new  = fmaxf(m_run, mt);
        float factor = __expf(m_run - m_new);
        float lsum = 0.f;
        for (int j = g; j < 64; j += 4) {
            float p = __expf(Ss[r * S_P + j] - m_new);
            Ss[r * S_P + j] = p;
            lsum += p;
        }
        lsum += __shfl_xor_sync(0xffffffffu, lsum, 1);
        lsum += __shfl_xor_sync(0xffffffffu, lsum, 2);
        l_run = l_run * factor + lsum;
        m_run = m_new;
        if (g == 0) rowfac[r] = factor;
        __syncthreads();

#pragma unroll
        for (int i = 0; i < 4; i++) {
            float f = rowfac[i0 + i];
#pragma unroll
            for (int c = 0; c < 8; c++) oacc[i][c] *= f;
        }

#pragma unroll 2
        for (int j = 0; j < 64; j++) {
            float4 va = *(const float4*)(Vs + j * V_P + j0);
            float4 wv = *(const float4*)(Vs + j * V_P + 64 + j0);
            float vv[8];
            vv[0] = va.x; vv[1] = va.y; vv[2] = va.z; vv[3] = va.w;
            vv[4] = wv.x; vv[5] = wv.y; vv[6] = wv.z; vv[7] = wv.w;
#pragma unroll
            for (int i = 0; i < 4; i++) {
                float p = Ss[(i0 + i) * S_P + j];
#pragma unroll
                for (int c = 0; c < 8; c++) oacc[i][c] += p * vv[c];
            }
        }
    }

    if (g == 0) rowl[r] = l_run;
    __syncthreads();

#pragma unroll
    for (int i = 0; i < 4; i++) {
        float inv_l = 1.f / rowl[i0 + i];
        float* orow = ctx + base_bh + (size_t)(q0 + i0 + i) * DD;
        float4 oa;
        float4 ob;
        oa.x = oacc[i][0] * inv_l; oa.y = oacc[i][1] * inv_l;
        oa.z = oacc[i][2] * inv_l; oa.w = oacc[i][3] * inv_l;
        ob.x = oacc[i][4] * inv_l; ob.y = oacc[i][5] * inv_l;
        ob.z = oacc[i][6] * inv_l; ob.w = oacc[i][7] * inv_l;
        *(float4*)(orow + j0)      = oa;
        *(float4*)(orow + 64 + j0) = ob;
    }
}

// ---------------------------------------------------------------------------
// Launch
// ---------------------------------------------------------------------------
static void split_launch(const float* src, __nv_bfloat16* hi,
                         __nv_bfloat16* lo, size_t n)
{
    int n4 = (int)(n / 4);
    split_kernel<<<(n4 + 255) / 256, 256>>>(src, hi, lo, n4);
}

extern "C" void kernel_launch(void* const* d_in, const int* in_sizes, int n_in,
                              void* d_out, int out_size)
{
    const float* x    = (const float*)d_in[0];
    const float* wq   = (const float*)d_in[1];
    const float* wdkv = (const float*)d_in[2];
    const float* wuk  = (const float*)d_in[3];
    const float* wuv  = (const float*)d_in[4];
    const float* wo   = (const float*)d_in[5];
    const float* bo   = (const float*)d_in[6];
    float* out = (float*)d_out;

    float *qb, *kb, *vb, *ctxb, *latb;
    cudaGetSymbolAddress((void**)&qb,   g_q);
    cudaGetSymbolAddress((void**)&kb,   g_k);
    cudaGetSymbolAddress((void**)&vb,   g_v);
    cudaGetSymbolAddress((void**)&ctxb, g_ctx);
    cudaGetSymbolAddress((void**)&latb, g_latent);

    __nv_bfloat16 *xh, *xl, *wqh, *wql, *wdh, *wdl, *wukh, *wukl;
    __nv_bfloat16 *wuvh, *wuvl, *woh, *wol, *lath, *latl, *ctxh, *ctxl;
    cudaGetSymbolAddress((void**)&xh,   g_x_hi);
    cudaGetSymbolAddress((void**)&xl,   g_x_lo);
    cudaGetSymbolAddress((void**)&wqh,  g_wq_hi);
    cudaGetSymbolAddress((void**)&wql,  g_wq_lo);
    cudaGetSymbolAddress((void**)&wdh,  g_wdkv_hi);
    cudaGetSymbolAddress((void**)&wdl,  g_wdkv_lo);
    cudaGetSymbolAddress((void**)&wukh, g_wuk_hi);
    cudaGetSymbolAddress((void**)&wukl, g_wuk_lo);
    cudaGetSymbolAddress((void**)&wuvh, g_wuv_hi);
    cudaGetSymbolAddress((void**)&wuvl, g_wuv_lo);
    cudaGetSymbolAddress((void**)&woh,  g_wo_hi);
    cudaGetSymbolAddress((void**)&wol,  g_wo_lo);
    cudaGetSymbolAddress((void**)&lath, g_lat_hi);
    cudaGetSymbolAddress((void**)&latl, g_lat_lo);
    cudaGetSymbolAddress((void**)&ctxh, g_ctx_hi);
    cudaGetSymbolAddress((void**)&ctxl, g_ctx_lo);

    cudaFuncSetAttribute(flash_kernel,
                         cudaFuncAttributeMaxDynamicSharedMemorySize,
                         FA_SMEM_BYTES);
    cudaFuncSetAttribute(hgemm_split_nt,
                         cudaFuncAttributeMaxDynamicSharedMemorySize,
                         GEMM_SMEM_BYTES);

    split_launch(x,    xh,   xl,   (size_t)MROWS * DD);
    split_launch(wq,   wqh,  wql,  (size_t)DD * DD);
    split_launch(wdkv, wdh,  wdl,  (size_t)LL * DD);
    split_launch(wuk,  wukh, wukl, (size_t)DD * LL);
    split_launch(wuv,  wuvh, wuvl, (size_t)DD * LL);
    split_launch(wo,   woh,  wol,  (size_t)DD * DD);

    // latent = x @ wdkv^T
    hgemm_split_nt<<<dim3(LL / 128, MROWS / 128), 256, GEMM_SMEM_BYTES>>>(
        xh, xl, wdh, wdl, (const float*)0, latb, MROWS, LL, DD);
    split_launch(latb, lath, latl, (size_t)MROWS * LL);

    // q = x @ wq^T
    hgemm_split_nt<<<dim3(DD / 128, MROWS / 128), 256, GEMM_SMEM_BYTES>>>(
        xh, xl, wqh, wql, (const float*)0, qb, MROWS, DD, DD);
    // k = latent @ wuk^T
    hgemm_split_nt<<<dim3(DD / 128, MROWS / 128), 256, GEMM_SMEM_BYTES>>>(
        lath, latl, wukh, wukl, (const float*)0, kb, MROWS, DD, LL);
    // v = latent @ wuv^T
    hgemm_split_nt<<<dim3(DD / 128, MROWS / 128), 256, GEMM_SMEM_BYTES>>>(
        lath, latl, wuvh, wuvl, (const float*)0, vb, MROWS, DD, LL);

    // RoPE
    {
        int total = MROWS * HH * 64;
        rope_kernel<<<(total + 255) / 256, 256>>>(qb, kb);
    }

    // flash attention -> ctx
    flash_kernel<<<dim3(SS / 64, HH, BB), 256, FA_SMEM_BYTES>>>(qb, kb, vb, ctxb);

    // out = ctx @ wo^T + bo
    split_launch(ctxb, ctxh, ctxl, (size_t)MROWS * DD);
    hgemm_split_nt<<<dim3(DD / 128, MROWS / 128), 256, GEMM_SMEM_BYTES>>>(
        ctxh, ctxl, woh, wol, bo, out, MROWS, DD, DD);
}

// round 7
// speedup vs baseline: 3.1275x; 1.0278x over previous
#include <cuda_runtime.h>
#include <cuda_bf16.h>
#include <math.h>
#include <stdint.h>

// Problem constants: B=2, S=2048, D=2048, L=256, H=16, hd=128
#define BB   2
#define SS   2048
#define DD   2048
#define LL   256
#define HH   16
#define HD   128
#define MROWS (BB * SS)

// ---------------------------------------------------------------------------
// Scratch
// ---------------------------------------------------------------------------
__device__ float g_q[(size_t)MROWS * DD];
__device__ float g_k[(size_t)MROWS * DD];
__device__ float g_v[(size_t)MROWS * DD];
__device__ float g_ctx[(size_t)MROWS * DD];
__device__ float g_latent[(size_t)MROWS * LL];

__device__ __nv_bfloat16 g_x_hi[(size_t)MROWS * DD];
__device__ __nv_bfloat16 g_x_lo[(size_t)MROWS * DD];
__device__ __nv_bfloat16 g_wq_hi[(size_t)DD * DD];
__device__ __nv_bfloat16 g_wq_lo[(size_t)DD * DD];
__device__ __nv_bfloat16 g_wdkv_hi[(size_t)LL * DD];
__device__ __nv_bfloat16 g_wdkv_lo[(size_t)LL * DD];
__device__ __nv_bfloat16 g_wuk_hi[(size_t)DD * LL];
__device__ __nv_bfloat16 g_wuk_lo[(size_t)DD * LL];
__device__ __nv_bfloat16 g_wuv_hi[(size_t)DD * LL];
__device__ __nv_bfloat16 g_wuv_lo[(size_t)DD * LL];
__device__ __nv_bfloat16 g_wo_hi[(size_t)DD * DD];
__device__ __nv_bfloat16 g_wo_lo[(size_t)DD * DD];
__device__ __nv_bfloat16 g_lat_hi[(size_t)MROWS * LL];
__device__ __nv_bfloat16 g_lat_lo[(size_t)MROWS * LL];
__device__ __nv_bfloat16 g_ctx_hi[(size_t)MROWS * DD];
__device__ __nv_bfloat16 g_ctx_lo[(size_t)MROWS * DD];

// ---------------------------------------------------------------------------
// Split fp32 -> bf16 hi + lo planes.
// ---------------------------------------------------------------------------
__global__ __launch_bounds__(256) void split_kernel(
    const float* __restrict__ src, __nv_bfloat16* __restrict__ hi,
    __nv_bfloat16* __restrict__ lo, int n4)
{
    int i = blockIdx.x * blockDim.x + threadIdx.x;
    if (i >= n4) return;
    float4 v = ((const float4*)src)[i];
    float vv[4];
    vv[0] = v.x; vv[1] = v.y; vv[2] = v.z; vv[3] = v.w;
    __nv_bfloat16 h[4];
    __nv_bfloat16 l[4];
#pragma unroll
    for (int c = 0; c < 4; c++) {
        h[c] = __float2bfloat16(vv[c]);
        l[c] = __float2bfloat16(vv[c] - __bfloat162float(h[c]));
    }
    *(uint2*)(hi + (size_t)i * 4) = *(uint2*)h;
    *(uint2*)(lo + (size_t)i * 4) = *(uint2*)l;
}

// ---------------------------------------------------------------------------
// HMMA / async helpers
// ---------------------------------------------------------------------------
__device__ __forceinline__ uint32_t su32(const void* p) {
    return (uint32_t)__cvta_generic_to_shared(p);
}
__device__ __forceinline__ void ldsm4(uint32_t* r, uint32_t a) {
    asm volatile("ldmatrix.sync.aligned.m8n8.x4.shared.b16 {%0,%1,%2,%3},[%4];"
                 : "=r"(r[0]), "=r"(r[1]), "=r"(r[2]), "=r"(r[3]) : "r"(a));
}
__device__ __forceinline__ void mma16816(float* d, const uint32_t* a,
                                         const uint32_t* b) {
    asm volatile(
        "mma.sync.aligned.m16n8k16.row.col.f32.bf16.bf16.f32 "
        "{%0,%1,%2,%3},{%4,%5,%6,%7},{%8,%9},{%0,%1,%2,%3};"
        : "+f"(d[0]), "+f"(d[1]), "+f"(d[2]), "+f"(d[3])
        : "r"(a[0]), "r"(a[1]), "r"(a[2]), "r"(a[3]), "r"(b[0]), "r"(b[1]));
}
__device__ __forceinline__ void cpa16(uint32_t saddr, const void* g) {
    asm volatile("cp.async.ca.shared.global [%0],[%1],16;"
                 :: "r"(saddr), "l"(g));
}
__device__ __forceinline__ void cp_commit() {
    asm volatile("cp.async.commit_group;");
}
template <int N>
__device__ __forceinline__ void cp_wait() {
    asm volatile("cp.async.wait_group %0;" :: "n"(N));
}

// ---------------------------------------------------------------------------
// Split-bf16 GEMM, 2-stage cp.async pipeline, 2 CTAs/SM.
// C[M,N] = A[M,K] @ B[N,K]^T (+bias), fp32 accumulate.
// 128x128x32 tile, 8 warps (2x4), warp tile 64x32. Terms: hh + hl + lh.
// ---------------------------------------------------------------------------
#define GP 40                       // smem pitch (bf16): conflict-free ldmatrix
#define PLANE (128 * GP)            // elems per plane
#define STAGES 2
#define GEMM_SMEM_BYTES (STAGES * 4 * PLANE * 2)

__global__ __launch_bounds__(256, 2) void hgemm_split_nt(
    const __nv_bfloat16* __restrict__ Ahi, const __nv_bfloat16* __restrict__ Alo,
    const __nv_bfloat16* __restrict__ Bhi, const __nv_bfloat16* __restrict__ Blo,
    const float* __restrict__ bias, float* __restrict__ C,
    int M, int N, int K)
{
    extern __shared__ __nv_bfloat16 smg[];

    const int t    = threadIdx.x;
    const int lane = t & 31;
    const int warp = t >> 5;
    const int wm   = warp >> 2;
    const int wn   = warp & 3;
    const int row0 = blockIdx.y * 128;
    const int col0 = blockIdx.x * 128;

    const int lrow = t >> 1;
    const int lk   = (t & 1) * 16;
    const __nv_bfloat16* pAh = Ahi + (size_t)(row0 + lrow) * K + lk;
    const __nv_bfloat16* pAl = Alo + (size_t)(row0 + lrow) * K + lk;
    const __nv_bfloat16* pBh = Bhi + (size_t)(col0 + lrow) * K + lk;
    const __nv_bfloat16* pBl = Blo + (size_t)(col0 + lrow) * K + lk;

    const int soff = lrow * GP + lk;
    const uint32_t smem_base = su32(smg);
    const int nkt = K / 32;

    float acc[4][4][4];
#pragma unroll
    for (int i = 0; i < 4; i++)
#pragma unroll
        for (int j = 0; j < 4; j++)
#pragma unroll
            for (int c = 0; c < 4; c++) acc[i][j][c] = 0.f;

#define FILL_STAGE(stg, ktv)                                                  \
    do {                                                                      \
        if ((ktv) < nkt) {                                                    \
            int adv = (ktv) * 32;                                             \
            uint32_t sb = smem_base + (uint32_t)(((stg) * 4) * PLANE + soff) * 2; \
            cpa16(sb,                    pAh + adv);                          \
            cpa16(sb + 16,               pAh + adv + 8);                      \
            cpa16(sb + PLANE * 2,        pAl + adv);                          \
            cpa16(sb + PLANE * 2 + 16,   pAl + adv + 8);                      \
            cpa16(sb + PLANE * 4,        pBh + adv);                          \
            cpa16(sb + PLANE * 4 + 16,   pBh + adv + 8);                      \
            cpa16(sb + PLANE * 6,        pBl + adv);                          \
            cpa16(sb + PLANE * 6 + 16,   pBl + adv + 8);                      \
        }                                                                     \
        cp_commit();                                                          \
    } while (0)

    // prologue: stage 0 in flight
    FILL_STAGE(0, 0);

    const int lm_r = (lane & 7) + ((lane >> 3) & 1) * 8;
    const int lm_c = (lane >> 4) * 8;

    for (int kt = 0; kt < nkt; kt++) {
        const int cur = kt & 1;
        cp_wait<0>();        // group kt complete (only pending group)
        __syncthreads();     // all warps done reading stage cur^1 (iter kt-1)

        // refill the stage consumed at kt-1 with chunk kt+1 (async)
        FILL_STAGE(cur ^ 1, kt + 1);

        const __nv_bfloat16* sAh = smg + (cur * 4 + 0) * PLANE;
        const __nv_bfloat16* sAl = smg + (cur * 4 + 1) * PLANE;
        const __nv_bfloat16* sBh = smg + (cur * 4 + 2) * PLANE;
        const __nv_bfloat16* sBl = smg + (cur * 4 + 3) * PLANE;

#pragma unroll
        for (int kc = 0; kc < 2; kc++) {
            const int c0 = kc * 16 + lm_c;
            uint32_t ah[4][4];
            uint32_t al[4][4];
            uint32_t bh[4][2];
            uint32_t bl[4][2];
#pragma unroll
            for (int mt = 0; mt < 4; mt++) {
                int r = wm * 64 + mt * 16 + lm_r;
                ldsm4(ah[mt], su32(sAh + r * GP + c0));
                ldsm4(al[mt], su32(sAl + r * GP + c0));
            }
#pragma unroll
            for (int np = 0; np < 2; np++) {
                int r = wn * 32 + np * 16 + lm_r;
                uint32_t tmp[4];
                ldsm4(tmp, su32(sBh + r * GP + c0));
                bh[2 * np][0]     = tmp[0]; bh[2 * np][1]     = tmp[2];
                bh[2 * np + 1][0] = tmp[1]; bh[2 * np + 1][1] = tmp[3];
                ldsm4(tmp, su32(sBl + r * GP + c0));
                bl[2 * np][0]     = tmp[0]; bl[2 * np][1]     = tmp[2];
                bl[2 * np + 1][0] = tmp[1]; bl[2 * np + 1][1] = tmp[3];
            }
#pragma unroll
            for (int mt = 0; mt < 4; mt++) {
#pragma unroll
                for (int nt = 0; nt < 4; nt++) {
                    mma16816(acc[mt][nt], ah[mt], bh[nt]);
                    mma16816(acc[mt][nt], ah[mt], bl[nt]);
                    mma16816(acc[mt][nt], al[mt], bh[nt]);
                }
            }
        }
    }

#pragma unroll
    for (int mt = 0; mt < 4; mt++) {
#pragma unroll
        for (int nt = 0; nt < 4; nt++) {
            int gr = row0 + wm * 64 + mt * 16 + (lane >> 2);
            int gc = col0 + wn * 32 + nt * 8 + (lane & 3) * 2;
            float b0 = 0.f;
            float b1 = 0.f;
            if (bias) { b0 = bias[gc]; b1 = bias[gc + 1]; }
            float2 o0;
            float2 o1;
            o0.x = acc[mt][nt][0] + b0; o0.y = acc[mt][nt][1] + b1;
            o1.x = acc[mt][nt][2] + b0; o1.y = acc[mt][nt][3] + b1;
            *(float2*)(C + (size_t)gr * N + gc)       = o0;
            *(float2*)(C + (size_t)(gr + 8) * N + gc) = o1;
        }
    }
#undef FILL_STAGE
}

// ---------------------------------------------------------------------------
// RoPE in-place on q and k.
// ---------------------------------------------------------------------------
__global__ __launch_bounds__(256) void rope_kernel(float* __restrict__ q,
                                                   float* __restrict__ k)
{
    int idx = blockIdx.x * blockDim.x + threadIdx.x;
    const int total = MROWS * HH * 64;
    if (idx >= total) return;

    int j   = idx & 63;
    int h   = (idx >> 6) & (HH - 1);
    int row = idx >> 10;
    int s   = row & (SS - 1);

    const float LOG2_BASE = 13.287712379549449f;
    float inv = exp2f(-(float)j * (LOG2_BASE / 64.0f));
    float ang = (float)s * inv;
    float c, sn;
    sincosf(ang, &sn, &c);

    size_t base = (size_t)row * DD + h * HD;

    float q1 = q[base + j];
    float q2 = q[base + j + 64];
    q[base + j]      = q1 * c - q2 * sn;
    q[base + j + 64] = q2 * c + q1 * sn;

    float k1 = k[base + j];
    float k2 = k[base + j + 64];
    k[base + j]      = k1 * c - k2 * sn;
    k[base + j + 64] = k2 * c + k1 * sn;
}

// ---------------------------------------------------------------------------
// Causal flash attention, fp32 FMA (unchanged).
// ---------------------------------------------------------------------------
#define QK_P 68
#define V_P  132
#define S_P  68
#define FA_SMEM_FLOATS (2 * 128 * QK_P + 64 * V_P + 64 * S_P + 128)
#define FA_SMEM_BYTES  (FA_SMEM_FLOATS * 4)

__global__ __launch_bounds__(256) void flash_kernel(
    const float* __restrict__ q, const float* __restrict__ k,
    const float* __restrict__ v, float* __restrict__ ctx)
{
    extern __shared__ float smf[];
    float* Qt = smf;
    float* Kt = Qt + 128 * QK_P;
    float* Vs = Kt + 128 * QK_P;
    float* Ss = Vs + 64 * V_P;
    float* rowfac = Ss + 64 * S_P;
    float* rowl   = rowfac + 64;

    const int qt = blockIdx.x;
    const int h  = blockIdx.y;
    const int b  = blockIdx.z;
    const int t  = threadIdx.x;

    const int q0 = qt * 64;
    const size_t base_bh = (size_t)b * SS * DD + (size_t)h * HD;

    for (int e = t; e < 64 * 32; e += 256) {
        int row = e >> 5;
        int c4  = (e & 31) * 4;
        float4 val = *(const float4*)(q + base_bh + (size_t)(q0 + row) * DD + c4);
        Qt[(c4 + 0) * QK_P + row] = val.x;
        Qt[(c4 + 1) * QK_P + row] = val.y;
        Qt[(c4 + 2) * QK_P + row] = val.z;
        Qt[(c4 + 3) * QK_P + row] = val.w;
    }

    const int ty = t >> 4;
    const int tx = t & 15;
    const int i0 = ty * 4;
    const int j0 = tx * 4;
    const int r  = t >> 2;
    const int g  = t & 3;

    float m_run = -1e30f;
    float l_run = 0.f;
    float oacc[4][8];
#pragma unroll
    for (int i = 0; i < 4; i++)
#pragma unroll
        for (int c = 0; c < 8; c++) oacc[i][c] = 0.f;

    const float scale = 0.088388347648318447f;

    for (int kt = 0; kt <= qt; kt++) {
        __syncthreads();
        for (int e = t; e < 64 * 32; e += 256) {
            int row = e >> 5;
            int c4  = (e & 31) * 4;
            size_t gidx = base_bh + (size_t)(kt * 64 + row) * DD + c4;
            float4 kv4 = *(const float4*)(k + gidx);
            Kt[(c4 + 0) * QK_P + row] = kv4.x;
            Kt[(c4 + 1) * QK_P + row] = kv4.y;
            Kt[(c4 + 2) * QK_P + row] = kv4.z;
            Kt[(c4 + 3) * QK_P + row] = kv4.w;
            *(float4*)(Vs + row * V_P + c4) = *(const float4*)(v + gidx);
        }
        __syncthreads();

        float sacc[4][4];
#pragma unroll
        for (int ii = 0; ii < 4; ii++)
#pragma unroll
            for (int jj = 0; jj < 4; jj++) sacc[ii][jj] = 0.f;

#pragma unroll 4
        for (int kk = 0; kk < HD; kk++) {
            float4 qv = *(const float4*)(Qt + kk * QK_P + i0);
            float4 kv = *(const float4*)(Kt + kk * QK_P + j0);
            float aa[4];
            float bb[4];
            aa[0] = qv.x; aa[1] = qv.y; aa[2] = qv.z; aa[3] = qv.w;
            bb[0] = kv.x; bb[1] = kv.y; bb[2] = kv.z; bb[3] = kv.w;
#pragma unroll
            for (int ii = 0; ii < 4; ii++)
#pragma unroll
                for (int jj = 0; jj < 4; jj++)
                    sacc[ii][jj] += aa[ii] * bb[jj];
        }

#pragma unroll
        for (int ii = 0; ii < 4; ii++) {
            int gi = q0 + i0 + ii;
            float sv[4];
#pragma unroll
            for (int jj = 0; jj < 4; jj++) {
                int gj = kt * 64 + j0 + jj;
                sv[jj] = (gj <= gi) ? sacc[ii][jj] * scale : -1e30f;
            }
            float4 svv;
            svv.x = sv[0]; svv.y = sv[1]; svv.z = sv[2]; svv.w = sv[3];
            *(float4*)(Ss + (i0 + ii) * S_P + j0) = svv;
        }
        __syncthreads();

        float mt = -1e30f;
        for (int j = g; j < 64; j += 4)
            mt = fmaxf(mt, Ss[r * S_P + j]);
        mt = fmaxf(mt, __shfl_xor_sync(0xffffffffu, mt, 1));
        mt = fmaxf(mt, __shfl_xor_sync(0xffffffffu, mt, 2));

        float m_new  = fmaxf(m_run, mt);
        float factor = __expf(m_run - m_new);
        float lsum = 0.f;
        for (int j = g; j < 64; j += 4) {
            float p = __expf(Ss[r * S_P + j] - m_new);
            Ss[r * S_P + j] = p;
            lsum += p;
        }
        lsum += __shfl_xor_sync(0xffffffffu, lsum, 1);
        lsum += __shfl_xor_sync(0xffffffffu, lsum, 2);
        l_run = l_run * factor + lsum;
        m_run = m_new;
        if (g == 0) rowfac[r] = factor;
        __syncthreads();

#pragma unroll
        for (int i = 0; i < 4; i++) {
            float f = rowfac[i0 + i];
#pragma unroll
            for (int c = 0; c < 8; c++) oacc[i][c] *= f;
        }

#pragma unroll 2
        for (int j = 0; j < 64; j++) {
            float4 va = *(const float4*)(Vs + j * V_P + j0);
            float4 wv = *(const float4*)(Vs + j * V_P + 64 + j0);
            float vv[8];
            vv[0] = va.x; vv[1] = va.y; vv[2] = va.z; vv[3] = va.w;
            vv[4] = wv.x; vv[5] = wv.y; vv[6] = wv.z; vv[7] = wv.w;
#pragma unroll
            for (int i = 0; i < 4; i++) {
                float p = Ss[(i0 + i) * S_P + j];
#pragma unroll
                for (int c = 0; c < 8; c++) oacc[i][c] += p * vv[c];
            }
        }
    }

    if (g == 0) rowl[r] = l_run;
    __syncthreads();

#pragma unroll
    for (int i = 0; i < 4; i++) {
        float inv_l = 1.f / rowl[i0 + i];
        float* orow = ctx + base_bh + (size_t)(q0 + i0 + i) * DD;
        float4 oa;
        float4 ob;
        oa.x = oacc[i][0] * inv_l; oa.y = oacc[i][1] * inv_l;
        oa.z = oacc[i][2] * inv_l; oa.w = oacc[i][3] * inv_l;
        ob.x = oacc[i][4] * inv_l; ob.y = oacc[i][5] * inv_l;
        ob.z = oacc[i][6] * inv_l; ob.w = oacc[i][7] * inv_l;
        *(float4*)(orow + j0)      = oa;
        *(float4*)(orow + 64 + j0) = ob;
    }
}

// ---------------------------------------------------------------------------
// Launch
// ---------------------------------------------------------------------------
static void split_launch(const float* src, __nv_bfloat16* hi,
                         __nv_bfloat16* lo, size_t n)
{
    int n4 = (int)(n / 4);
    split_kernel<<<(n4 + 255) / 256, 256>>>(src, hi, lo, n4);
}

extern "C" void kernel_launch(void* const* d_in, const int* in_sizes, int n_in,
                              void* d_out, int out_size)
{
    const float* x    = (const float*)d_in[0];
    const float* wq   = (const float*)d_in[1];
    const float* wdkv = (const float*)d_in[2];
    const float* wuk  = (const float*)d_in[3];
    const float* wuv  = (const float*)d_in[4];
    const float* wo   = (const float*)d_in[5];
    const float* bo   = (const float*)d_in[6];
    float* out = (float*)d_out;

    float *qb, *kb, *vb, *ctxb, *latb;
    cudaGetSymbolAddress((void**)&qb,   g_q);
    cudaGetSymbolAddress((void**)&kb,   g_k);
    cudaGetSymbolAddress((void**)&vb,   g_v);
    cudaGetSymbolAddress((void**)&ctxb, g_ctx);
    cudaGetSymbolAddress((void**)&latb, g_latent);

    __nv_bfloat16 *xh, *xl, *wqh, *wql, *wdh, *wdl, *wukh, *wukl;
    __nv_bfloat16 *wuvh, *wuvl, *woh, *wol, *lath, *latl, *ctxh, *ctxl;
    cudaGetSymbolAddress((void**)&xh,   g_x_hi);
    cudaGetSymbolAddress((void**)&xl,   g_x_lo);
    cudaGetSymbolAddress((void**)&wqh,  g_wq_hi);
    cudaGetSymbolAddress((void**)&wql,  g_wq_lo);
    cudaGetSymbolAddress((void**)&wdh,  g_wdkv_hi);
    cudaGetSymbolAddress((void**)&wdl,  g_wdkv_lo);
    cudaGetSymbolAddress((void**)&wukh, g_wuk_hi);
    cudaGetSymbolAddress((void**)&wukl, g_wuk_lo);
    cudaGetSymbolAddress((void**)&wuvh, g_wuv_hi);
    cudaGetSymbolAddress((void**)&wuvl, g_wuv_lo);
    cudaGetSymbolAddress((void**)&woh,  g_wo_hi);
    cudaGetSymbolAddress((void**)&wol,  g_wo_lo);
    cudaGetSymbolAddress((void**)&lath, g_lat_hi);
    cudaGetSymbolAddress((void**)&latl, g_lat_lo);
    cudaGetSymbolAddress((void**)&ctxh, g_ctx_hi);
    cudaGetSymbolAddress((void**)&ctxl, g_ctx_lo);

    cudaFuncSetAttribute(flash_kernel,
                         cudaFuncAttributeMaxDynamicSharedMemorySize,
                         FA_SMEM_BYTES);
    cudaFuncSetAttribute(hgemm_split_nt,
                         cudaFuncAttributeMaxDynamicSharedMemorySize,
                         GEMM_SMEM_BYTES);

    split_launch(x,    xh,   xl,   (size_t)MROWS * DD);
    split_launch(wq,   wqh,  wql,  (size_t)DD * DD);
    split_launch(wdkv, wdh,  wdl,  (size_t)LL * DD);
    split_launch(wuk,  wukh, wukl, (size_t)DD * LL);
    split_launch(wuv,  wuvh, wuvl, (size_t)DD * LL);
    split_launch(wo,   woh,  wol,  (size_t)DD * DD);

    // latent = x @ wdkv^T
    hgemm_split_nt<<<dim3(LL / 128, MROWS / 128), 256, GEMM_SMEM_BYTES>>>(
        xh, xl, wdh, wdl, (const float*)0, latb, MROWS, LL, DD);
    split_launch(latb, lath, latl, (size_t)MROWS * LL);

    // q = x @ wq^T
    hgemm_split_nt<<<dim3(DD / 128, MROWS / 128), 256, GEMM_SMEM_BYTES>>>(
        xh, xl, wqh, wql, (const float*)0, qb, MROWS, DD, DD);
    // k = latent @ wuk^T
    hgemm_split_nt<<<dim3(DD / 128, MROWS / 128), 256, GEMM_SMEM_BYTES>>>(
        lath, latl, wukh, wukl, (const float*)0, kb, MROWS, DD, LL);
    // v = latent @ wuv^T
    hgemm_split_nt<<<dim3(DD / 128, MROWS / 128), 256, GEMM_SMEM_BYTES>>>(
        lath, latl, wuvh, wuvl, (const float*)0, vb, MROWS, DD, LL);

    // RoPE
    {
        int total = MROWS * HH * 64;
        rope_kernel<<<(total + 255) / 256, 256>>>(qb, kb);
    }

    // flash attention -> ctx
    flash_kernel<<<dim3(SS / 64, HH, BB), 256, FA_SMEM_BYTES>>>(qb, kb, vb, ctxb);

    // out = ctx @ wo^T + bo
    split_launch(ctxb, ctxh, ctxl, (size_t)MROWS * DD);
    hgemm_split_nt<<<dim3(DD / 128, MROWS / 128), 256, GEMM_SMEM_BYTES>>>(
        ctxh, ctxl, woh, wol, bo, out, MROWS, DD, DD);
}